// round 1
// baseline (speedup 1.0000x reference)
#include <cuda_runtime.h>
#include <math.h>
#include <stdint.h>

// Problem constants
#define BB   2
#define SS   1024
#define DD   768
#define HH   12
#define DHH  64
#define LL   6
#define FF   3072
#define RELV 32
#define NROW (BB*SS)          // 2048 token rows

// ---------------------------------------------------------------------------
// Scratch (device globals; no dynamic allocation allowed)
// ---------------------------------------------------------------------------
__device__ float g_x  [NROW*DD];
__device__ float g_h  [NROW*DD];
__device__ float g_q  [NROW*DD];
__device__ float g_k  [NROW*DD];
__device__ float g_v  [NROW*DD];
__device__ float g_ctx[NROW*DD];
__device__ float g_scores[(size_t)BB*HH*SS*SS];   // also reused as probs
__device__ float g_rel[(size_t)BB*HH*SS*RELV];
__device__ float g_ffn[(size_t)NROW*FF];

// ---------------------------------------------------------------------------
// Block reductions (256 threads)
// ---------------------------------------------------------------------------
__device__ __forceinline__ float bsum256(float v) {
    __shared__ float sm[8];
    #pragma unroll
    for (int o = 16; o; o >>= 1) v += __shfl_xor_sync(0xffffffffu, v, o);
    if ((threadIdx.x & 31) == 0) sm[threadIdx.x >> 5] = v;
    __syncthreads();
    float r = 0.f;
    #pragma unroll
    for (int i = 0; i < 8; i++) r += sm[i];
    __syncthreads();
    return r;
}

__device__ __forceinline__ float bmax256(float v) {
    __shared__ float sm[8];
    #pragma unroll
    for (int o = 16; o; o >>= 1) v = fmaxf(v, __shfl_xor_sync(0xffffffffu, v, o));
    if ((threadIdx.x & 31) == 0) sm[threadIdx.x >> 5] = v;
    __syncthreads();
    float r = -3.0e38f;
    #pragma unroll
    for (int i = 0; i < 8; i++) r = fmaxf(r, sm[i]);
    __syncthreads();
    return r;
}

// ---------------------------------------------------------------------------
// Embedding: tok + seg + sinusoidal(pos*qm)*qm
// grid = NROW, block = 256
// ---------------------------------------------------------------------------
__global__ void embed_kernel(const int* __restrict__ token_ids,
                             const int* __restrict__ segment_ids,
                             const int* __restrict__ position_ids,
                             const int* __restrict__ question_mask,
                             const float* __restrict__ tok_emb,
                             const float* __restrict__ seg_emb,
                             float* __restrict__ x)
{
    int row = blockIdx.x;
    int tok = token_ids[row];
    int seg = segment_ids[row];
    int qmi = question_mask[row];
    float qm = (float)qmi;
    int pos = position_ids[row] * qmi;
    float fpos = (float)pos;

    const float* te = tok_emb + (size_t)tok * DD;
    const float* se = seg_emb + (size_t)seg * DD;
    float* xr = x + (size_t)row * DD;

    for (int i = threadIdx.x; i < DD; i += 256) {
        float ex  = (float)(2 * (i >> 1)) * (1.0f / (float)DD);
        float inv = __powf(10000.0f, -ex);
        float ang = fpos * inv;
        float pe  = (i & 1) ? cosf(ang) : sinf(ang);
        xr[i] = te[i] + se[i] + pe * qm;
    }
}

// ---------------------------------------------------------------------------
// LayerNorm (two-pass, eps = 1e-12). grid = NROW, block = 256, 3 elems/thread
// ---------------------------------------------------------------------------
__global__ void ln_kernel(const float* __restrict__ x,
                          const float* __restrict__ gamma,
                          const float* __restrict__ beta,
                          float* __restrict__ out)
{
    int row = blockIdx.x;
    const float* xr = x + (size_t)row * DD;
    int t = threadIdx.x;
    float v0 = xr[t], v1 = xr[t + 256], v2 = xr[t + 512];

    float s = bsum256(v0 + v1 + v2);
    float mu = s * (1.0f / (float)DD);
    float d0 = v0 - mu, d1 = v1 - mu, d2 = v2 - mu;
    float s2 = bsum256(d0*d0 + d1*d1 + d2*d2);
    float var = s2 * (1.0f / (float)DD);
    float rstd = rsqrtf(var + 1e-12f);

    float* orow = out + (size_t)row * DD;
    orow[t]       = d0 * rstd * gamma[t]       + beta[t];
    orow[t + 256] = d1 * rstd * gamma[t + 256] + beta[t + 256];
    orow[t + 512] = d2 * rstd * gamma[t + 512] + beta[t + 512];
}

// ---------------------------------------------------------------------------
// Generic GEMM: C[M,N] = A[M,K] @ W[K,N] + bias  (+epilogue)
// EPI: 0 = bias only, 1 = bias+gelu(tanh), 2 = bias+residual
// 64x64 tile, BK=16, block (16,16), 4x4 per thread. M,N %64==0, K %16==0.
// ---------------------------------------------------------------------------
template<int EPI>
__global__ void gemm_kernel(const float* __restrict__ A,
                            const float* __restrict__ W,
                            const float* __restrict__ bias,
                            const float* __restrict__ R,
                            float* __restrict__ C,
                            int M, int N, int K)
{
    __shared__ float As[16][65];
    __shared__ float Bs[16][65];

    int tx = threadIdx.x, ty = threadIdx.y;
    int tid = ty * 16 + tx;
    int m0 = blockIdx.y * 64, n0 = blockIdx.x * 64;

    float acc[4][4] = {};

    for (int k0 = 0; k0 < K; k0 += 16) {
        #pragma unroll
        for (int e = 0; e < 4; e++) {
            int idx = tid + e * 256;
            int m  = idx >> 4, kk = idx & 15;
            As[kk][m] = A[(size_t)(m0 + m) * K + k0 + kk];
            int kk2 = idx >> 6, n = idx & 63;
            Bs[kk2][n] = W[(size_t)(k0 + kk2) * N + n0 + n];
        }
        __syncthreads();
        #pragma unroll
        for (int kk = 0; kk < 16; kk++) {
            float a[4], b[4];
            #pragma unroll
            for (int i = 0; i < 4; i++) a[i] = As[kk][ty * 4 + i];
            #pragma unroll
            for (int j = 0; j < 4; j++) b[j] = Bs[kk][tx * 4 + j];
            #pragma unroll
            for (int i = 0; i < 4; i++)
                #pragma unroll
                for (int j = 0; j < 4; j++)
                    acc[i][j] += a[i] * b[j];
        }
        __syncthreads();
    }

    #pragma unroll
    for (int i = 0; i < 4; i++) {
        int m = m0 + ty * 4 + i;
        #pragma unroll
        for (int j = 0; j < 4; j++) {
            int n = n0 + tx * 4 + j;
            float v = acc[i][j] + bias[n];
            if (EPI == 1) {
                float u = 0.7978845608028654f * (v + 0.044715f * v * v * v);
                v = 0.5f * v * (1.0f + tanhf(u));
            }
            if (EPI == 2) v += R[(size_t)m * N + n];
            C[(size_t)m * N + n] = v;
        }
    }
}

// ---------------------------------------------------------------------------
// Attention scores: scores[bh,i,j] = sum_d q[b,i,h,d] * k[b,j,h,d]  (raw dot)
// grid (S/64, S/64, B*H), block (16,16)
// ---------------------------------------------------------------------------
__global__ void scores_kernel(const float* __restrict__ q,
                              const float* __restrict__ k,
                              float* __restrict__ scores)
{
    int bh = blockIdx.z;
    int b = bh / HH, h = bh % HH;
    const float* Q  = q + (size_t)b * SS * DD + h * DHH;
    const float* Kp = k + (size_t)b * SS * DD + h * DHH;
    int i0 = blockIdx.y * 64, j0 = blockIdx.x * 64;

    __shared__ float Qs[64][65];
    __shared__ float Ks[64][65];

    int tx = threadIdx.x, ty = threadIdx.y;
    int tid = ty * 16 + tx;

    #pragma unroll
    for (int e = 0; e < 16; e++) {
        int idx = tid + e * 256;
        int r = idx >> 6, d = idx & 63;
        Qs[r][d] = Q [(size_t)(i0 + r) * DD + d];
        Ks[r][d] = Kp[(size_t)(j0 + r) * DD + d];
    }
    __syncthreads();

    float acc[4][4] = {};
    #pragma unroll 8
    for (int d = 0; d < 64; d++) {
        float a[4], bv[4];
        #pragma unroll
        for (int i = 0; i < 4; i++) a[i]  = Qs[ty * 4 + i][d];
        #pragma unroll
        for (int j = 0; j < 4; j++) bv[j] = Ks[tx * 4 + j][d];
        #pragma unroll
        for (int i = 0; i < 4; i++)
            #pragma unroll
            for (int j = 0; j < 4; j++)
                acc[i][j] += a[i] * bv[j];
    }

    float* sp = scores + (size_t)bh * SS * SS;
    #pragma unroll
    for (int i = 0; i < 4; i++) {
        int m = i0 + ty * 4 + i;
        #pragma unroll
        for (int j = 0; j < 4; j++)
            sp[(size_t)m * SS + j0 + tx * 4 + j] = acc[i][j];
    }
}

// ---------------------------------------------------------------------------
// Relative bias: rel[bh,i,r] = sum_d q[b,i,h,d] * rel_emb[r,h,d]
// grid (S/8, B*H), block 256 (= 8 i-rows x 32 r)
// ---------------------------------------------------------------------------
__global__ void rel_kernel(const float* __restrict__ q,
                           const float* __restrict__ relw,   // [RELV,H,DH] for this layer
                           float* __restrict__ rel)
{
    int bh = blockIdx.y;
    int b = bh / HH, h = bh % HH;
    int i0 = blockIdx.x * 8;

    __shared__ float Rs[RELV][65];
    __shared__ float Qs[8][DHH];

    int tid = threadIdx.x;
    #pragma unroll
    for (int e = 0; e < 8; e++) {
        int idx = tid + e * 256;
        int r = idx >> 6, d = idx & 63;
        Rs[r][d] = relw[((size_t)r * HH + h) * DHH + d];
    }
    #pragma unroll
    for (int e = 0; e < 2; e++) {
        int idx = tid + e * 256;
        int ii = idx >> 6, d = idx & 63;
        Qs[ii][d] = q[(size_t)b * SS * DD + (size_t)(i0 + ii) * DD + h * DHH + d];
    }
    __syncthreads();

    int r = tid & 31, iy = tid >> 5;
    float s = 0.f;
    #pragma unroll
    for (int d = 0; d < 64; d++) s += Qs[iy][d] * Rs[r][d];
    rel[((size_t)bh * SS + i0 + iy) * RELV + r] = s;
}

// ---------------------------------------------------------------------------
// Fused: probs = softmax((scores + rel[ids]) * scale + (1-mask)*-1e4), in place
// grid = B*H*S rows, block 256, 4 cols/thread
// ---------------------------------------------------------------------------
__global__ void softmax_kernel(float* __restrict__ scores,
                               const float* __restrict__ rel,
                               const int* __restrict__ rel_ids,
                               const int* __restrict__ mask)
{
    int row = blockIdx.x;          // = bh*S + i
    int bh = row >> 10;
    int i  = row & (SS - 1);
    int b  = bh / HH;

    float* sp = scores + (size_t)row * SS;
    const float* rl  = rel + (size_t)row * RELV;
    const int* idr = rel_ids + ((size_t)b * SS + i) * SS;
    const int* mr  = mask    + ((size_t)b * SS + i) * SS;

    __shared__ float rs[RELV];
    if (threadIdx.x < RELV) rs[threadIdx.x] = rl[threadIdx.x];
    __syncthreads();

    float vals[4];
    float mx = -3.0e38f;
    #pragma unroll
    for (int t = 0; t < 4; t++) {
        int j = threadIdx.x + t * 256;
        float v = (sp[j] + rs[idr[j]]) * 0.125f
                + (1.0f - (float)mr[j]) * (-10000.0f);
        vals[t] = v;
        mx = fmaxf(mx, v);
    }
    mx = bmax256(mx);
    float se = 0.f;
    #pragma unroll
    for (int t = 0; t < 4; t++) { vals[t] = expf(vals[t] - mx); se += vals[t]; }
    se = bsum256(se);
    float inv = 1.0f / se;
    #pragma unroll
    for (int t = 0; t < 4; t++) sp[threadIdx.x + t * 256] = vals[t] * inv;
}

// ---------------------------------------------------------------------------
// Context: ctx[b,i,h,d] = sum_j probs[bh,i,j] * v[b,j,h,d]
// grid (S/64, 1, B*H), block (16,16)
// ---------------------------------------------------------------------------
__global__ void ctx_kernel(const float* __restrict__ probs,
                           const float* __restrict__ v,
                           float* __restrict__ ctx)
{
    int bh = blockIdx.z;
    int b = bh / HH, h = bh % HH;
    int i0 = blockIdx.x * 64;
    const float* P = probs + (size_t)bh * SS * SS;
    const float* V = v + (size_t)b * SS * DD + h * DHH;

    __shared__ float Ps[16][65];
    __shared__ float Vs[16][65];

    int tx = threadIdx.x, ty = threadIdx.y;
    int tid = ty * 16 + tx;
    float acc[4][4] = {};

    for (int j0 = 0; j0 < SS; j0 += 16) {
        #pragma unroll
        for (int e = 0; e < 4; e++) {
            int idx = tid + e * 256;
            int m = idx >> 4, kk = idx & 15;
            Ps[kk][m] = P[(size_t)(i0 + m) * SS + j0 + kk];
            int kk2 = idx >> 6, d = idx & 63;
            Vs[kk2][d] = V[(size_t)(j0 + kk2) * DD + d];
        }
        __syncthreads();
        #pragma unroll
        for (int kk = 0; kk < 16; kk++) {
            float a[4], bv[4];
            #pragma unroll
            for (int i = 0; i < 4; i++) a[i]  = Ps[kk][ty * 4 + i];
            #pragma unroll
            for (int j = 0; j < 4; j++) bv[j] = Vs[kk][tx * 4 + j];
            #pragma unroll
            for (int i = 0; i < 4; i++)
                #pragma unroll
                for (int j = 0; j < 4; j++)
                    acc[i][j] += a[i] * bv[j];
        }
        __syncthreads();
    }

    #pragma unroll
    for (int i = 0; i < 4; i++) {
        int m = i0 + ty * 4 + i;
        #pragma unroll
        for (int j = 0; j < 4; j++) {
            int n = tx * 4 + j;
            ctx[(size_t)b * SS * DD + (size_t)m * DD + h * DHH + n] = acc[i][j];
        }
    }
}

// ---------------------------------------------------------------------------
// Launch
// ---------------------------------------------------------------------------
extern "C" void kernel_launch(void* const* d_in, const int* in_sizes, int n_in,
                              void* d_out, int out_size)
{
    const int* token_ids     = (const int*)d_in[0];
    const int* segment_ids   = (const int*)d_in[1];
    const int* position_ids  = (const int*)d_in[2];
    const int* question_mask = (const int*)d_in[3];
    const int* attention_mask= (const int*)d_in[4];
    const int* rel_ids       = (const int*)d_in[5];
    const float* tok_emb = (const float*)d_in[6];
    const float* seg_emb = (const float*)d_in[7];
    const float* ln1_g = (const float*)d_in[8];
    const float* ln1_b = (const float*)d_in[9];
    const float* ln2_g = (const float*)d_in[10];
    const float* ln2_b = (const float*)d_in[11];
    const float* wq = (const float*)d_in[12];
    const float* bq = (const float*)d_in[13];
    const float* wk = (const float*)d_in[14];
    const float* bk = (const float*)d_in[15];
    const float* wv = (const float*)d_in[16];
    const float* bv = (const float*)d_in[17];
    const float* wo = (const float*)d_in[18];
    const float* bo = (const float*)d_in[19];
    const float* rel_emb = (const float*)d_in[20];
    const float* w1 = (const float*)d_in[21];
    const float* b1 = (const float*)d_in[22];
    const float* w2 = (const float*)d_in[23];
    const float* b2 = (const float*)d_in[24];

    float *x, *h, *q, *k, *v, *ctx, *sc, *rl, *ff;
    cudaGetSymbolAddress((void**)&x,   g_x);
    cudaGetSymbolAddress((void**)&h,   g_h);
    cudaGetSymbolAddress((void**)&q,   g_q);
    cudaGetSymbolAddress((void**)&k,   g_k);
    cudaGetSymbolAddress((void**)&v,   g_v);
    cudaGetSymbolAddress((void**)&ctx, g_ctx);
    cudaGetSymbolAddress((void**)&sc,  g_scores);
    cudaGetSymbolAddress((void**)&rl,  g_rel);
    cudaGetSymbolAddress((void**)&ff,  g_ffn);

    dim3 blk(16, 16);

    embed_kernel<<<NROW, 256>>>(token_ids, segment_ids, position_ids,
                                question_mask, tok_emb, seg_emb, x);

    for (int l = 0; l < LL; l++) {
        const float* wq_l = wq + (size_t)l * DD * DD;
        const float* wk_l = wk + (size_t)l * DD * DD;
        const float* wv_l = wv + (size_t)l * DD * DD;
        const float* wo_l = wo + (size_t)l * DD * DD;
        const float* w1_l = w1 + (size_t)l * DD * FF;
        const float* w2_l = w2 + (size_t)l * FF * DD;

        // --- attention block ---
        ln_kernel<<<NROW, 256>>>(x, ln1_g + l * DD, ln1_b + l * DD, h);

        gemm_kernel<0><<<dim3(DD / 64, NROW / 64), blk>>>(h, wq_l, bq + l * DD, nullptr, q, NROW, DD, DD);
        gemm_kernel<0><<<dim3(DD / 64, NROW / 64), blk>>>(h, wk_l, bk + l * DD, nullptr, k, NROW, DD, DD);
        gemm_kernel<0><<<dim3(DD / 64, NROW / 64), blk>>>(h, wv_l, bv + l * DD, nullptr, v, NROW, DD, DD);

        scores_kernel<<<dim3(SS / 64, SS / 64, BB * HH), blk>>>(q, k, sc);
        rel_kernel<<<dim3(SS / 8, BB * HH), 256>>>(q, rel_emb + (size_t)l * RELV * HH * DHH, rl);
        softmax_kernel<<<BB * HH * SS, 256>>>(sc, rl, rel_ids, attention_mask);
        ctx_kernel<<<dim3(SS / 64, 1, BB * HH), blk>>>(sc, v, ctx);

        gemm_kernel<2><<<dim3(DD / 64, NROW / 64), blk>>>(ctx, wo_l, bo + l * DD, x, x, NROW, DD, DD);

        // --- FFN block ---
        ln_kernel<<<NROW, 256>>>(x, ln2_g + l * DD, ln2_b + l * DD, h);
        gemm_kernel<1><<<dim3(FF / 64, NROW / 64), blk>>>(h, w1_l, b1 + l * FF, nullptr, ff, NROW, FF, DD);

        float* outp = (l == LL - 1) ? (float*)d_out : x;
        gemm_kernel<2><<<dim3(DD / 64, NROW / 64), blk>>>(ff, w2_l, b2 + l * DD, x, outp, NROW, DD, FF);
    }
}

// round 2
// speedup vs baseline: 1.8389x; 1.8389x over previous
#include <cuda_runtime.h>
#include <math.h>
#include <stdint.h>

// Problem constants
#define BB   2
#define SS   1024
#define DD   768
#define HH   12
#define DHH  64
#define LL   6
#define FF   3072
#define RELV 32
#define NROW (BB*SS)          // 2048 token rows

// ---------------------------------------------------------------------------
// Scratch (device globals; no dynamic allocation allowed)
// ---------------------------------------------------------------------------
__device__ float g_x  [NROW*DD];
__device__ float g_h  [NROW*DD];
__device__ float g_q  [NROW*DD];
__device__ float g_k  [NROW*DD];
__device__ float g_v  [NROW*DD];
__device__ float g_ctx[NROW*DD];
__device__ float g_scores[(size_t)BB*HH*SS*SS];   // also reused as probs
__device__ float g_rel[(size_t)BB*HH*SS*RELV];
__device__ float g_ffn[(size_t)NROW*FF];

// ---------------------------------------------------------------------------
// tf32 helpers
// ---------------------------------------------------------------------------
__device__ __forceinline__ void tf32_split(float v, uint32_t& hi, uint32_t& lo) {
    uint32_t b = __float_as_uint(v);
    hi = b & 0xffffe000u;
    lo = __float_as_uint(v - __uint_as_float(hi));
}

__device__ __forceinline__ void mma_tf32(float c[4], const uint32_t a[4], const uint32_t b[2]) {
    asm volatile(
        "mma.sync.aligned.m16n8k8.row.col.f32.tf32.tf32.f32 "
        "{%0,%1,%2,%3},{%4,%5,%6,%7},{%8,%9},{%0,%1,%2,%3};"
        : "+f"(c[0]), "+f"(c[1]), "+f"(c[2]), "+f"(c[3])
        : "r"(a[0]), "r"(a[1]), "r"(a[2]), "r"(a[3]),
          "r"(b[0]), "r"(b[1]));
}

__device__ __forceinline__ float gelu_tanh(float v) {
    float u = 0.7978845608028654f * (v + 0.044715f * v * v * v);
    return 0.5f * v * (1.0f + tanhf(u));
}

// ---------------------------------------------------------------------------
// Tensor-core GEMM core (3xTF32 split => ~fp32 accuracy)
// C[M,N] = A[M,K] @ op(B) + epilogue
//   TRB=false: B is [K,N] row-major.  TRB=true: B is [N,K] row-major (B^T).
// Block: 256 threads = 8 warps. Block tile BM x BN, warp tile WM x WN.
// EPI: 0=+bias, 1=+bias+gelu, 2=+bias+residual, 3=raw
// Requires M%BM==0, N%BN==0, K%16==0.
// ---------------------------------------------------------------------------
template<int BM, int BN, int WM, int WN, bool TRB, int EPI>
__device__ __forceinline__ void gemm_core(
    const float* __restrict__ A, int lda,
    const float* __restrict__ B, int ldb,
    const float* __restrict__ bias,
    const float* __restrict__ R, int ldr,
    float* __restrict__ C, int ldc,
    int K, int m0, int n0)
{
    constexpr int NWN = BN / WN;            // warps along N
    constexpr int NMT = WM / 16;            // m16 tiles per warp
    constexpr int NNT = WN / 8;             // n8 tiles per warp
    constexpr int NA4 = (BM * 16) / 1024;   // float4 A loads per thread
    constexpr int NB4 = (BN * 16) / 1024;   // float4 B loads per thread

    __shared__ __align__(16) float As[16][BM + 8];
    __shared__ __align__(16) float Bs[16][BN + 8];

    const int tid  = threadIdx.x;
    const int lane = tid & 31;
    const int wid  = tid >> 5;
    const int g    = lane >> 2;
    const int t    = lane & 3;
    const int wm   = (wid / NWN) * WM;
    const int wn   = (wid % NWN) * WN;

    const float* Ap = A + (size_t)m0 * lda;
    const float* Bp = TRB ? (B + (size_t)n0 * ldb) : (B + n0);

    float acc[NMT][NNT][4];
    #pragma unroll
    for (int i = 0; i < NMT; i++)
        #pragma unroll
        for (int j = 0; j < NNT; j++)
            #pragma unroll
            for (int e = 0; e < 4; e++) acc[i][j][e] = 0.f;

    float4 rA[NA4], rB[NB4];

    auto gload = [&](int k0) {
        #pragma unroll
        for (int e = 0; e < NA4; e++) {
            int f = tid + e * 256;
            rA[e] = *reinterpret_cast<const float4*>(
                Ap + (size_t)(f >> 2) * lda + k0 + (f & 3) * 4);
        }
        #pragma unroll
        for (int e = 0; e < NB4; e++) {
            int f = tid + e * 256;
            if (TRB)
                rB[e] = *reinterpret_cast<const float4*>(
                    Bp + (size_t)(f >> 2) * ldb + k0 + (f & 3) * 4);
            else
                rB[e] = *reinterpret_cast<const float4*>(
                    Bp + (size_t)(k0 + f / (BN / 4)) * ldb + (f % (BN / 4)) * 4);
        }
    };

    auto sstore = [&]() {
        #pragma unroll
        for (int e = 0; e < NA4; e++) {
            int f = tid + e * 256; int m = f >> 2; int kq = (f & 3) * 4;
            As[kq + 0][m] = rA[e].x; As[kq + 1][m] = rA[e].y;
            As[kq + 2][m] = rA[e].z; As[kq + 3][m] = rA[e].w;
        }
        #pragma unroll
        for (int e = 0; e < NB4; e++) {
            int f = tid + e * 256;
            if (TRB) {
                int n = f >> 2; int kq = (f & 3) * 4;
                Bs[kq + 0][n] = rB[e].x; Bs[kq + 1][n] = rB[e].y;
                Bs[kq + 2][n] = rB[e].z; Bs[kq + 3][n] = rB[e].w;
            } else {
                int kk = f / (BN / 4); int nq = (f % (BN / 4)) * 4;
                *reinterpret_cast<float4*>(&Bs[kk][nq]) = rB[e];
            }
        }
    };

    gload(0);
    sstore();
    __syncthreads();

    const int ntiles = K >> 4;
    for (int kt = 0; kt < ntiles; kt++) {
        const bool more = (kt + 1 < ntiles);
        if (more) gload((kt + 1) << 4);

        #pragma unroll
        for (int k8 = 0; k8 < 16; k8 += 8) {
            uint32_t ah[NMT][4], al[NMT][4];
            uint32_t bfh[NNT][2], bfl[NNT][2];
            #pragma unroll
            for (int mt = 0; mt < NMT; mt++) {
                int r = wm + mt * 16 + g;
                tf32_split(As[k8 + t][r],         ah[mt][0], al[mt][0]);
                tf32_split(As[k8 + t][r + 8],     ah[mt][1], al[mt][1]);
                tf32_split(As[k8 + t + 4][r],     ah[mt][2], al[mt][2]);
                tf32_split(As[k8 + t + 4][r + 8], ah[mt][3], al[mt][3]);
            }
            #pragma unroll
            for (int nt = 0; nt < NNT; nt++) {
                int c = wn + nt * 8 + g;
                tf32_split(Bs[k8 + t][c],     bfh[nt][0], bfl[nt][0]);
                tf32_split(Bs[k8 + t + 4][c], bfh[nt][1], bfl[nt][1]);
            }
            #pragma unroll
            for (int mt = 0; mt < NMT; mt++)
                #pragma unroll
                for (int nt = 0; nt < NNT; nt++) {
                    mma_tf32(acc[mt][nt], ah[mt], bfh[nt]);
                    mma_tf32(acc[mt][nt], al[mt], bfh[nt]);
                    mma_tf32(acc[mt][nt], ah[mt], bfl[nt]);
                }
        }
        __syncthreads();
        if (more) { sstore(); __syncthreads(); }
    }

    // Epilogue
    #pragma unroll
    for (int mt = 0; mt < NMT; mt++) {
        int r0 = m0 + wm + mt * 16 + g;
        #pragma unroll
        for (int nt = 0; nt < NNT; nt++) {
            int cc = n0 + wn + nt * 8 + t * 2;
            float2 p0 = make_float2(acc[mt][nt][0], acc[mt][nt][1]);
            float2 p1 = make_float2(acc[mt][nt][2], acc[mt][nt][3]);
            if (EPI != 3) {
                float b0 = bias[cc], b1 = bias[cc + 1];
                p0.x += b0; p0.y += b1; p1.x += b0; p1.y += b1;
            }
            if (EPI == 1) {
                p0.x = gelu_tanh(p0.x); p0.y = gelu_tanh(p0.y);
                p1.x = gelu_tanh(p1.x); p1.y = gelu_tanh(p1.y);
            }
            if (EPI == 2) {
                p0.x += R[(size_t)r0 * ldr + cc];
                p0.y += R[(size_t)r0 * ldr + cc + 1];
                p1.x += R[(size_t)(r0 + 8) * ldr + cc];
                p1.y += R[(size_t)(r0 + 8) * ldr + cc + 1];
            }
            *reinterpret_cast<float2*>(&C[(size_t)r0 * ldc + cc]) = p0;
            *reinterpret_cast<float2*>(&C[(size_t)(r0 + 8) * ldc + cc]) = p1;
        }
    }
}

// ---------------------------------------------------------------------------
// GEMM wrappers
// ---------------------------------------------------------------------------
// QKV fused via blockIdx.z: grid(6,16,3)
__global__ __launch_bounds__(256, 1)
void qkv_kernel(const float* __restrict__ h,
                const float* __restrict__ wq, const float* __restrict__ wk,
                const float* __restrict__ wv,
                const float* __restrict__ bq, const float* __restrict__ bk,
                const float* __restrict__ bv,
                float* __restrict__ q, float* __restrict__ k, float* __restrict__ v)
{
    int z = blockIdx.z;
    const float* W  = (z == 0) ? wq : (z == 1) ? wk : wv;
    const float* bi = (z == 0) ? bq : (z == 1) ? bk : bv;
    float* C        = (z == 0) ? q  : (z == 1) ? k  : v;
    gemm_core<128,128,64,32,false,0>(h, DD, W, DD, bi, nullptr, 0, C, DD,
                                     DD, blockIdx.y * 128, blockIdx.x * 128);
}

template<int EPI>
__global__ __launch_bounds__(256, 1)
void mm_kernel(const float* __restrict__ A, int lda,
               const float* __restrict__ B, int ldb,
               const float* __restrict__ bias,
               const float* __restrict__ R, int ldr,
               float* __restrict__ C, int ldc, int K)
{
    gemm_core<128,128,64,32,false,EPI>(A, lda, B, ldb, bias, R, ldr, C, ldc,
                                       K, blockIdx.y * 128, blockIdx.x * 128);
}

// scores[bh,i,j] = sum_d q[b,i,h,d] k[b,j,h,d]; grid(8,8,24)
__global__ __launch_bounds__(256, 1)
void scores_tc_kernel(const float* __restrict__ q, const float* __restrict__ k,
                      float* __restrict__ sc)
{
    int bh = blockIdx.z;
    int b = bh / HH, h = bh % HH;
    const float* Qp = q + (size_t)b * SS * DD + h * DHH;
    const float* Kp = k + (size_t)b * SS * DD + h * DHH;
    float* Cp = sc + (size_t)bh * SS * SS;
    gemm_core<128,128,64,32,true,3>(Qp, DD, Kp, DD, nullptr, nullptr, 0,
                                    Cp, SS, DHH, blockIdx.y * 128, blockIdx.x * 128);
}

// ctx[b,i,h,d] = sum_j probs[bh,i,j] v[b,j,h,d]; grid(1,8,24)
__global__ __launch_bounds__(256, 1)
void ctx_tc_kernel(const float* __restrict__ p, const float* __restrict__ v,
                   float* __restrict__ ctx)
{
    int bh = blockIdx.z;
    int b = bh / HH, h = bh % HH;
    const float* Pp = p + (size_t)bh * SS * SS;
    const float* Vp = v + (size_t)b * SS * DD + h * DHH;
    float* Cp = ctx + (size_t)b * SS * DD + h * DHH;
    gemm_core<128,64,32,32,false,3>(Pp, SS, Vp, DD, nullptr, nullptr, 0,
                                    Cp, DD, SS, blockIdx.y * 128, blockIdx.x * 64);
}

// ---------------------------------------------------------------------------
// Block reductions (256 threads)
// ---------------------------------------------------------------------------
__device__ __forceinline__ float bsum256(float v) {
    __shared__ float sm[8];
    #pragma unroll
    for (int o = 16; o; o >>= 1) v += __shfl_xor_sync(0xffffffffu, v, o);
    if ((threadIdx.x & 31) == 0) sm[threadIdx.x >> 5] = v;
    __syncthreads();
    float r = 0.f;
    #pragma unroll
    for (int i = 0; i < 8; i++) r += sm[i];
    __syncthreads();
    return r;
}

__device__ __forceinline__ float bmax256(float v) {
    __shared__ float sm[8];
    #pragma unroll
    for (int o = 16; o; o >>= 1) v = fmaxf(v, __shfl_xor_sync(0xffffffffu, v, o));
    if ((threadIdx.x & 31) == 0) sm[threadIdx.x >> 5] = v;
    __syncthreads();
    float r = -3.0e38f;
    #pragma unroll
    for (int i = 0; i < 8; i++) r = fmaxf(r, sm[i]);
    __syncthreads();
    return r;
}

// ---------------------------------------------------------------------------
// Embedding
// ---------------------------------------------------------------------------
__global__ void embed_kernel(const int* __restrict__ token_ids,
                             const int* __restrict__ segment_ids,
                             const int* __restrict__ position_ids,
                             const int* __restrict__ question_mask,
                             const float* __restrict__ tok_emb,
                             const float* __restrict__ seg_emb,
                             float* __restrict__ x)
{
    int row = blockIdx.x;
    int tok = token_ids[row];
    int seg = segment_ids[row];
    int qmi = question_mask[row];
    float qm = (float)qmi;
    int pos = position_ids[row] * qmi;
    float fpos = (float)pos;

    const float* te = tok_emb + (size_t)tok * DD;
    const float* se = seg_emb + (size_t)seg * DD;
    float* xr = x + (size_t)row * DD;

    for (int i = threadIdx.x; i < DD; i += 256) {
        float ex  = (float)(2 * (i >> 1)) * (1.0f / (float)DD);
        float inv = __powf(10000.0f, -ex);
        float ang = fpos * inv;
        float pe  = (i & 1) ? cosf(ang) : sinf(ang);
        xr[i] = te[i] + se[i] + pe * qm;
    }
}

// ---------------------------------------------------------------------------
// LayerNorm
// ---------------------------------------------------------------------------
__global__ void ln_kernel(const float* __restrict__ x,
                          const float* __restrict__ gamma,
                          const float* __restrict__ beta,
                          float* __restrict__ out)
{
    int row = blockIdx.x;
    const float* xr = x + (size_t)row * DD;
    int t = threadIdx.x;
    float v0 = xr[t], v1 = xr[t + 256], v2 = xr[t + 512];

    float s = bsum256(v0 + v1 + v2);
    float mu = s * (1.0f / (float)DD);
    float d0 = v0 - mu, d1 = v1 - mu, d2 = v2 - mu;
    float s2 = bsum256(d0*d0 + d1*d1 + d2*d2);
    float var = s2 * (1.0f / (float)DD);
    float rstd = rsqrtf(var + 1e-12f);

    float* orow = out + (size_t)row * DD;
    orow[t]       = d0 * rstd * gamma[t]       + beta[t];
    orow[t + 256] = d1 * rstd * gamma[t + 256] + beta[t + 256];
    orow[t + 512] = d2 * rstd * gamma[t + 512] + beta[t + 512];
}

// ---------------------------------------------------------------------------
// Relative bias: rel[bh,i,r] = sum_d q[b,i,h,d] * rel_emb[r,h,d]
// ---------------------------------------------------------------------------
__global__ void rel_kernel(const float* __restrict__ q,
                           const float* __restrict__ relw,
                           float* __restrict__ rel)
{
    int bh = blockIdx.y;
    int b = bh / HH, h = bh % HH;
    int i0 = blockIdx.x * 8;

    __shared__ float Rs[RELV][65];
    __shared__ float Qs[8][DHH];

    int tid = threadIdx.x;
    #pragma unroll
    for (int e = 0; e < 8; e++) {
        int idx = tid + e * 256;
        int r = idx >> 6, d = idx & 63;
        Rs[r][d] = relw[((size_t)r * HH + h) * DHH + d];
    }
    #pragma unroll
    for (int e = 0; e < 2; e++) {
        int idx = tid + e * 256;
        int ii = idx >> 6, d = idx & 63;
        Qs[ii][d] = q[(size_t)b * SS * DD + (size_t)(i0 + ii) * DD + h * DHH + d];
    }
    __syncthreads();

    int r = tid & 31, iy = tid >> 5;
    float s = 0.f;
    #pragma unroll
    for (int d = 0; d < 64; d++) s += Qs[iy][d] * Rs[r][d];
    rel[((size_t)bh * SS + i0 + iy) * RELV + r] = s;
}

// ---------------------------------------------------------------------------
// Fused softmax. grid = B*S*H (h innermost for rel_ids/mask L2 reuse)
// ---------------------------------------------------------------------------
__global__ void softmax_kernel(float* __restrict__ scores,
                               const float* __restrict__ rel,
                               const int* __restrict__ rel_ids,
                               const int* __restrict__ mask)
{
    int blk = blockIdx.x;
    int h  = blk % HH;
    int bi = blk / HH;
    int b  = bi >> 10;
    int i  = bi & (SS - 1);
    int row = ((b * HH + h) << 10) + i;     // bh*S + i

    float* sp = scores + (size_t)row * SS;
    const float* rl = rel + (size_t)row * RELV;
    const int* idr = rel_ids + ((size_t)b * SS + i) * SS;
    const int* mr  = mask    + ((size_t)b * SS + i) * SS;

    __shared__ float rs[RELV];
    if (threadIdx.x < RELV) rs[threadIdx.x] = rl[threadIdx.x];
    __syncthreads();

    float vals[4];
    float mx = -3.0e38f;
    #pragma unroll
    for (int t = 0; t < 4; t++) {
        int j = threadIdx.x + t * 256;
        float v = (sp[j] + rs[idr[j]]) * 0.125f
                + (1.0f - (float)mr[j]) * (-10000.0f);
        vals[t] = v;
        mx = fmaxf(mx, v);
    }
    mx = bmax256(mx);
    float se = 0.f;
    #pragma unroll
    for (int t = 0; t < 4; t++) { vals[t] = expf(vals[t] - mx); se += vals[t]; }
    se = bsum256(se);
    float inv = 1.0f / se;
    #pragma unroll
    for (int t = 0; t < 4; t++) sp[threadIdx.x + t * 256] = vals[t] * inv;
}

// ---------------------------------------------------------------------------
// Launch
// ---------------------------------------------------------------------------
extern "C" void kernel_launch(void* const* d_in, const int* in_sizes, int n_in,
                              void* d_out, int out_size)
{
    const int* token_ids     = (const int*)d_in[0];
    const int* segment_ids   = (const int*)d_in[1];
    const int* position_ids  = (const int*)d_in[2];
    const int* question_mask = (const int*)d_in[3];
    const int* attention_mask= (const int*)d_in[4];
    const int* rel_ids       = (const int*)d_in[5];
    const float* tok_emb = (const float*)d_in[6];
    const float* seg_emb = (const float*)d_in[7];
    const float* ln1_g = (const float*)d_in[8];
    const float* ln1_b = (const float*)d_in[9];
    const float* ln2_g = (const float*)d_in[10];
    const float* ln2_b = (const float*)d_in[11];
    const float* wq = (const float*)d_in[12];
    const float* bq = (const float*)d_in[13];
    const float* wk = (const float*)d_in[14];
    const float* bk = (const float*)d_in[15];
    const float* wv = (const float*)d_in[16];
    const float* bv = (const float*)d_in[17];
    const float* wo = (const float*)d_in[18];
    const float* bo = (const float*)d_in[19];
    const float* rel_emb = (const float*)d_in[20];
    const float* w1 = (const float*)d_in[21];
    const float* b1 = (const float*)d_in[22];
    const float* w2 = (const float*)d_in[23];
    const float* b2 = (const float*)d_in[24];

    float *x, *h, *q, *k, *v, *ctx, *sc, *rl, *ff;
    cudaGetSymbolAddress((void**)&x,   g_x);
    cudaGetSymbolAddress((void**)&h,   g_h);
    cudaGetSymbolAddress((void**)&q,   g_q);
    cudaGetSymbolAddress((void**)&k,   g_k);
    cudaGetSymbolAddress((void**)&v,   g_v);
    cudaGetSymbolAddress((void**)&ctx, g_ctx);
    cudaGetSymbolAddress((void**)&sc,  g_scores);
    cudaGetSymbolAddress((void**)&rl,  g_rel);
    cudaGetSymbolAddress((void**)&ff,  g_ffn);

    embed_kernel<<<NROW, 256>>>(token_ids, segment_ids, position_ids,
                                question_mask, tok_emb, seg_emb, x);

    for (int l = 0; l < LL; l++) {
        const float* wq_l = wq + (size_t)l * DD * DD;
        const float* wk_l = wk + (size_t)l * DD * DD;
        const float* wv_l = wv + (size_t)l * DD * DD;
        const float* wo_l = wo + (size_t)l * DD * DD;
        const float* w1_l = w1 + (size_t)l * DD * FF;
        const float* w2_l = w2 + (size_t)l * FF * DD;

        // --- attention block ---
        ln_kernel<<<NROW, 256>>>(x, ln1_g + l * DD, ln1_b + l * DD, h);

        qkv_kernel<<<dim3(DD / 128, NROW / 128, 3), 256>>>(
            h, wq_l, wk_l, wv_l, bq + l * DD, bk + l * DD, bv + l * DD, q, k, v);

        scores_tc_kernel<<<dim3(SS / 128, SS / 128, BB * HH), 256>>>(q, k, sc);
        rel_kernel<<<dim3(SS / 8, BB * HH), 256>>>(
            q, rel_emb + (size_t)l * RELV * HH * DHH, rl);
        softmax_kernel<<<BB * SS * HH, 256>>>(sc, rl, rel_ids, attention_mask);
        ctx_tc_kernel<<<dim3(1, SS / 128, BB * HH), 256>>>(sc, v, ctx);

        mm_kernel<2><<<dim3(DD / 128, NROW / 128), 256>>>(
            ctx, DD, wo_l, DD, bo + l * DD, x, DD, x, DD, DD);

        // --- FFN block ---
        ln_kernel<<<NROW, 256>>>(x, ln2_g + l * DD, ln2_b + l * DD, h);
        mm_kernel<1><<<dim3(FF / 128, NROW / 128), 256>>>(
            h, DD, w1_l, FF, b1 + l * FF, nullptr, 0, ff, FF, DD);

        float* outp = (l == LL - 1) ? (float*)d_out : x;
        mm_kernel<2><<<dim3(DD / 128, NROW / 128), 256>>>(
            ff, FF, w2_l, DD, b2 + l * DD, x, DD, outp, DD, FF);
    }
}

// round 3
// speedup vs baseline: 2.0400x; 1.1093x over previous
#include <cuda_runtime.h>
#include <cuda_fp16.h>
#include <math.h>
#include <stdint.h>

// Problem constants
#define BB   2
#define SS   1024
#define DD   768
#define HH   12
#define DHH  64
#define LL   6
#define FF   3072
#define RELV 32
#define NROW (BB*SS)          // 2048 token rows

// ---------------------------------------------------------------------------
// Scratch (device globals; no dynamic allocation allowed)
// ---------------------------------------------------------------------------
__device__ float g_x  [NROW*DD];
__device__ float g_h  [NROW*DD];
__device__ float g_q  [NROW*DD];
__device__ float g_k  [NROW*DD];
__device__ float g_v  [NROW*DD];
__device__ float g_ctx[NROW*DD];
__device__ float g_rel[(size_t)BB*HH*SS*RELV];
__device__ float g_ffn[(size_t)NROW*FF];

// ---------------------------------------------------------------------------
// tf32 / mma helpers
// ---------------------------------------------------------------------------
__device__ __forceinline__ void tf32_split(float v, uint32_t& hi, uint32_t& lo) {
    uint32_t b = __float_as_uint(v);
    hi = b & 0xffffe000u;
    lo = __float_as_uint(v - __uint_as_float(hi));
}

__device__ __forceinline__ void mma_tf32(float c[4], const uint32_t a[4], const uint32_t b[2]) {
    asm volatile(
        "mma.sync.aligned.m16n8k8.row.col.f32.tf32.tf32.f32 "
        "{%0,%1,%2,%3},{%4,%5,%6,%7},{%8,%9},{%0,%1,%2,%3};"
        : "+f"(c[0]), "+f"(c[1]), "+f"(c[2]), "+f"(c[3])
        : "r"(a[0]), "r"(a[1]), "r"(a[2]), "r"(a[3]),
          "r"(b[0]), "r"(b[1]));
}

__device__ __forceinline__ void mma_f16(float c[4], uint32_t a0, uint32_t a1,
                                        uint32_t a2, uint32_t a3,
                                        uint32_t b0, uint32_t b1) {
    asm volatile(
        "mma.sync.aligned.m16n8k16.row.col.f32.f16.f16.f32 "
        "{%0,%1,%2,%3},{%4,%5,%6,%7},{%8,%9},{%0,%1,%2,%3};"
        : "+f"(c[0]), "+f"(c[1]), "+f"(c[2]), "+f"(c[3])
        : "r"(a0), "r"(a1), "r"(a2), "r"(a3), "r"(b0), "r"(b1));
}

__device__ __forceinline__ float gelu_tanh(float v) {
    float u = 0.7978845608028654f * (v + 0.044715f * v * v * v);
    return 0.5f * v * (1.0f + tanhf(u));
}

// ---------------------------------------------------------------------------
// Tensor-core GEMM core (3xTF32 split => ~fp32 accuracy)
// ---------------------------------------------------------------------------
template<int BM, int BN, int WM, int WN, bool TRB, int EPI>
__device__ __forceinline__ void gemm_core(
    const float* __restrict__ A, int lda,
    const float* __restrict__ B, int ldb,
    const float* __restrict__ bias,
    const float* __restrict__ R, int ldr,
    float* __restrict__ C, int ldc,
    int K, int m0, int n0)
{
    constexpr int NWN = BN / WN;
    constexpr int NMT = WM / 16;
    constexpr int NNT = WN / 8;
    constexpr int NA4 = (BM * 16) / 1024;
    constexpr int NB4 = (BN * 16) / 1024;

    __shared__ __align__(16) float As[16][BM + 8];
    __shared__ __align__(16) float Bs[16][BN + 8];

    const int tid  = threadIdx.x;
    const int lane = tid & 31;
    const int wid  = tid >> 5;
    const int g    = lane >> 2;
    const int t    = lane & 3;
    const int wm   = (wid / NWN) * WM;
    const int wn   = (wid % NWN) * WN;

    const float* Ap = A + (size_t)m0 * lda;
    const float* Bp = TRB ? (B + (size_t)n0 * ldb) : (B + n0);

    float acc[NMT][NNT][4];
    #pragma unroll
    for (int i = 0; i < NMT; i++)
        #pragma unroll
        for (int j = 0; j < NNT; j++)
            #pragma unroll
            for (int e = 0; e < 4; e++) acc[i][j][e] = 0.f;

    float4 rA[NA4], rB[NB4];

    auto gload = [&](int k0) {
        #pragma unroll
        for (int e = 0; e < NA4; e++) {
            int f = tid + e * 256;
            rA[e] = *reinterpret_cast<const float4*>(
                Ap + (size_t)(f >> 2) * lda + k0 + (f & 3) * 4);
        }
        #pragma unroll
        for (int e = 0; e < NB4; e++) {
            int f = tid + e * 256;
            if (TRB)
                rB[e] = *reinterpret_cast<const float4*>(
                    Bp + (size_t)(f >> 2) * ldb + k0 + (f & 3) * 4);
            else
                rB[e] = *reinterpret_cast<const float4*>(
                    Bp + (size_t)(k0 + f / (BN / 4)) * ldb + (f % (BN / 4)) * 4);
        }
    };

    auto sstore = [&]() {
        #pragma unroll
        for (int e = 0; e < NA4; e++) {
            int f = tid + e * 256; int m = f >> 2; int kq = (f & 3) * 4;
            As[kq + 0][m] = rA[e].x; As[kq + 1][m] = rA[e].y;
            As[kq + 2][m] = rA[e].z; As[kq + 3][m] = rA[e].w;
        }
        #pragma unroll
        for (int e = 0; e < NB4; e++) {
            int f = tid + e * 256;
            if (TRB) {
                int n = f >> 2; int kq = (f & 3) * 4;
                Bs[kq + 0][n] = rB[e].x; Bs[kq + 1][n] = rB[e].y;
                Bs[kq + 2][n] = rB[e].z; Bs[kq + 3][n] = rB[e].w;
            } else {
                int kk = f / (BN / 4); int nq = (f % (BN / 4)) * 4;
                *reinterpret_cast<float4*>(&Bs[kk][nq]) = rB[e];
            }
        }
    };

    gload(0);
    sstore();
    __syncthreads();

    const int ntiles = K >> 4;
    for (int kt = 0; kt < ntiles; kt++) {
        const bool more = (kt + 1 < ntiles);
        if (more) gload((kt + 1) << 4);

        #pragma unroll
        for (int k8 = 0; k8 < 16; k8 += 8) {
            uint32_t ah[NMT][4], al[NMT][4];
            uint32_t bfh[NNT][2], bfl[NNT][2];
            #pragma unroll
            for (int mt = 0; mt < NMT; mt++) {
                int r = wm + mt * 16 + g;
                tf32_split(As[k8 + t][r],         ah[mt][0], al[mt][0]);
                tf32_split(As[k8 + t][r + 8],     ah[mt][1], al[mt][1]);
                tf32_split(As[k8 + t + 4][r],     ah[mt][2], al[mt][2]);
                tf32_split(As[k8 + t + 4][r + 8], ah[mt][3], al[mt][3]);
            }
            #pragma unroll
            for (int nt = 0; nt < NNT; nt++) {
                int c = wn + nt * 8 + g;
                tf32_split(Bs[k8 + t][c],     bfh[nt][0], bfl[nt][0]);
                tf32_split(Bs[k8 + t + 4][c], bfh[nt][1], bfl[nt][1]);
            }
            #pragma unroll
            for (int mt = 0; mt < NMT; mt++)
                #pragma unroll
                for (int nt = 0; nt < NNT; nt++) {
                    mma_tf32(acc[mt][nt], ah[mt], bfh[nt]);
                    mma_tf32(acc[mt][nt], al[mt], bfh[nt]);
                    mma_tf32(acc[mt][nt], ah[mt], bfl[nt]);
                }
        }
        __syncthreads();
        if (more) { sstore(); __syncthreads(); }
    }

    #pragma unroll
    for (int mt = 0; mt < NMT; mt++) {
        int r0 = m0 + wm + mt * 16 + g;
        #pragma unroll
        for (int nt = 0; nt < NNT; nt++) {
            int cc = n0 + wn + nt * 8 + t * 2;
            float2 p0 = make_float2(acc[mt][nt][0], acc[mt][nt][1]);
            float2 p1 = make_float2(acc[mt][nt][2], acc[mt][nt][3]);
            if (EPI != 3) {
                float b0 = bias[cc], b1 = bias[cc + 1];
                p0.x += b0; p0.y += b1; p1.x += b0; p1.y += b1;
            }
            if (EPI == 1) {
                p0.x = gelu_tanh(p0.x); p0.y = gelu_tanh(p0.y);
                p1.x = gelu_tanh(p1.x); p1.y = gelu_tanh(p1.y);
            }
            if (EPI == 2) {
                p0.x += R[(size_t)r0 * ldr + cc];
                p0.y += R[(size_t)r0 * ldr + cc + 1];
                p1.x += R[(size_t)(r0 + 8) * ldr + cc];
                p1.y += R[(size_t)(r0 + 8) * ldr + cc + 1];
            }
            *reinterpret_cast<float2*>(&C[(size_t)r0 * ldc + cc]) = p0;
            *reinterpret_cast<float2*>(&C[(size_t)(r0 + 8) * ldc + cc]) = p1;
        }
    }
}

// QKV fused via blockIdx.z
__global__ __launch_bounds__(256, 1)
void qkv_kernel(const float* __restrict__ h,
                const float* __restrict__ wq, const float* __restrict__ wk,
                const float* __restrict__ wv,
                const float* __restrict__ bq, const float* __restrict__ bk,
                const float* __restrict__ bv,
                float* __restrict__ q, float* __restrict__ k, float* __restrict__ v)
{
    int z = blockIdx.z;
    const float* W  = (z == 0) ? wq : (z == 1) ? wk : wv;
    const float* bi = (z == 0) ? bq : (z == 1) ? bk : bv;
    float* C        = (z == 0) ? q  : (z == 1) ? k  : v;
    gemm_core<128,128,64,32,false,0>(h, DD, W, DD, bi, nullptr, 0, C, DD,
                                     DD, blockIdx.y * 128, blockIdx.x * 128);
}

template<int EPI>
__global__ __launch_bounds__(256, 1)
void mm_kernel(const float* __restrict__ A, int lda,
               const float* __restrict__ B, int ldb,
               const float* __restrict__ bias,
               const float* __restrict__ R, int ldr,
               float* __restrict__ C, int ldc, int K)
{
    gemm_core<128,128,64,32,false,EPI>(A, lda, B, ldb, bias, R, ldr, C, ldc,
                                       K, blockIdx.y * 128, blockIdx.x * 128);
}

// ---------------------------------------------------------------------------
// Fused flash attention: per CTA = 64 query rows of one (b,h).
// 128 threads = 4 warps, warp tile 16(i) x 128(j). Online softmax.
// S = QK^T via 3xTF32; P.V via fp16 m16n8k16 with register-resident P.
// ---------------------------------------------------------------------------
__global__ __launch_bounds__(128, 2)
void flash_kernel(const float* __restrict__ q, const float* __restrict__ k,
                  const float* __restrict__ v, const float* __restrict__ rel,
                  const int* __restrict__ rel_ids, const int* __restrict__ mask,
                  float* __restrict__ ctx)
{
    extern __shared__ float smf[];
    float*  Qs   = smf;                                  // [64][72]  Qs[d][row]
    float*  Ks   = smf + 4608;                           // [64][136] Ks[d][j]
    __half2* Vh  = reinterpret_cast<__half2*>(smf + 13312); // [64][72] Vh[jpair][d]
    float*  rels = smf + 17920;                          // [64][33]

    const int tid  = threadIdx.x;
    const int lane = tid & 31;
    const int wid  = tid >> 5;
    const int g = lane >> 2, t = lane & 3;
    const int wm = wid << 4;

    const int i0 = blockIdx.x * 64;
    const int bh = blockIdx.y;
    const int b = bh / HH, h = bh - b * HH;

    const float* Qp = q + (size_t)b * SS * DD + h * DHH;
    const float* Kp = k + (size_t)b * SS * DD + h * DHH;
    const float* Vp = v + (size_t)b * SS * DD + h * DHH;

    // Q tile -> Qs[d][row] (transposed). row-inner: conflict-free stores.
    {
        int row = tid & 63;
        int base = (tid >> 6) * 8;
        #pragma unroll
        for (int e = 0; e < 8; e++) {
            int dq = (base + e) * 4;
            float4 val = *reinterpret_cast<const float4*>(Qp + (size_t)(i0 + row) * DD + dq);
            Qs[(dq + 0) * 72 + row] = val.x;
            Qs[(dq + 1) * 72 + row] = val.y;
            Qs[(dq + 2) * 72 + row] = val.z;
            Qs[(dq + 3) * 72 + row] = val.w;
        }
    }
    // rel rows (precomputed) -> rels[row][r]
    {
        const float* rp = rel + ((size_t)bh * SS + i0) * RELV;
        #pragma unroll
        for (int e = 0; e < 4; e++) {
            int f = tid + e * 128;
            float4 val = *reinterpret_cast<const float4*>(rp + f * 4);
            int row = f >> 3, r = (f & 7) * 4;
            rels[row * 33 + r + 0] = val.x;
            rels[row * 33 + r + 1] = val.y;
            rels[row * 33 + r + 2] = val.z;
            rels[row * 33 + r + 3] = val.w;
        }
    }

    float m0r = -1e30f, m1r = -1e30f;
    float l0r = 0.f, l1r = 0.f;
    float oacc[8][4];
    #pragma unroll
    for (int nt = 0; nt < 8; nt++) {
        oacc[nt][0] = 0.f; oacc[nt][1] = 0.f; oacc[nt][2] = 0.f; oacc[nt][3] = 0.f;
    }

    const int ig0 = i0 + wm + g;
    const int ig1 = ig0 + 8;
    const int* rid0 = rel_ids + ((size_t)b * SS + ig0) * SS + 2 * t;
    const int* rid1 = rel_ids + ((size_t)b * SS + ig1) * SS + 2 * t;
    const int* mk0  = mask    + ((size_t)b * SS + ig0) * SS + 2 * t;
    const int* mk1  = mask    + ((size_t)b * SS + ig1) * SS + 2 * t;
    const float* rl0 = rels + (wm + g) * 33;
    const float* rl1 = rl0 + 8 * 33;

    for (int jt = 0; jt < 8; jt++) {
        const int j0 = jt * 128;
        __syncthreads();
        // K tile -> Ks[d][j] (transposed). j = tid: conflict-free stores.
        #pragma unroll
        for (int e = 0; e < 16; e++) {
            int dq = e * 4;
            float4 val = *reinterpret_cast<const float4*>(Kp + (size_t)(j0 + tid) * DD + dq);
            Ks[(dq + 0) * 136 + tid] = val.x;
            Ks[(dq + 1) * 136 + tid] = val.y;
            Ks[(dq + 2) * 136 + tid] = val.z;
            Ks[(dq + 3) * 136 + tid] = val.w;
        }
        // V tile -> Vh[jpair][d] as half2(v_j, v_{j+1}). dq-inner: coalesced gmem.
        #pragma unroll
        for (int e = 0; e < 8; e++) {
            int f = tid + e * 128;
            int jp = f >> 4, dq = (f & 15) * 4;
            float4 v0 = *reinterpret_cast<const float4*>(Vp + (size_t)(j0 + 2 * jp) * DD + dq);
            float4 v1 = *reinterpret_cast<const float4*>(Vp + (size_t)(j0 + 2 * jp + 1) * DD + dq);
            __half2* dst = Vh + jp * 72 + dq;
            dst[0] = __floats2half2_rn(v0.x, v1.x);
            dst[1] = __floats2half2_rn(v0.y, v1.y);
            dst[2] = __floats2half2_rn(v0.z, v1.z);
            dst[3] = __floats2half2_rn(v0.w, v1.w);
        }
        __syncthreads();

        // S = Q K^T, 16 n8-tiles per warp
        float sacc[16][4];
        #pragma unroll
        for (int nt = 0; nt < 16; nt++) {
            sacc[nt][0] = 0.f; sacc[nt][1] = 0.f; sacc[nt][2] = 0.f; sacc[nt][3] = 0.f;
        }
        #pragma unroll
        for (int kc = 0; kc < 8; kc++) {
            int k0 = kc * 8;
            uint32_t ah[4], al[4];
            tf32_split(Qs[(k0 + t) * 72 + wm + g],         ah[0], al[0]);
            tf32_split(Qs[(k0 + t) * 72 + wm + g + 8],     ah[1], al[1]);
            tf32_split(Qs[(k0 + t + 4) * 72 + wm + g],     ah[2], al[2]);
            tf32_split(Qs[(k0 + t + 4) * 72 + wm + g + 8], ah[3], al[3]);
            #pragma unroll
            for (int nt = 0; nt < 16; nt++) {
                uint32_t bh2[2], bl2[2];
                tf32_split(Ks[(k0 + t) * 136 + nt * 8 + g],     bh2[0], bl2[0]);
                tf32_split(Ks[(k0 + t + 4) * 136 + nt * 8 + g], bh2[1], bl2[1]);
                mma_tf32(sacc[nt], ah, bh2);
                mma_tf32(sacc[nt], al, bh2);
                mma_tf32(sacc[nt], ah, bl2);
            }
        }

        // rel-bias gather + mask + scale
        float mx0 = -1e30f, mx1 = -1e30f;
        #pragma unroll
        for (int nt = 0; nt < 16; nt++) {
            int jo = j0 + nt * 8;
            int2 i0v = *reinterpret_cast<const int2*>(rid0 + jo);
            int2 i1v = *reinterpret_cast<const int2*>(rid1 + jo);
            int2 m0v = *reinterpret_cast<const int2*>(mk0 + jo);
            int2 m1v = *reinterpret_cast<const int2*>(mk1 + jo);
            sacc[nt][0] = (sacc[nt][0] + rl0[i0v.x]) * 0.125f + (1.f - (float)m0v.x) * -10000.f;
            sacc[nt][1] = (sacc[nt][1] + rl0[i0v.y]) * 0.125f + (1.f - (float)m0v.y) * -10000.f;
            sacc[nt][2] = (sacc[nt][2] + rl1[i1v.x]) * 0.125f + (1.f - (float)m1v.x) * -10000.f;
            sacc[nt][3] = (sacc[nt][3] + rl1[i1v.y]) * 0.125f + (1.f - (float)m1v.y) * -10000.f;
            mx0 = fmaxf(mx0, fmaxf(sacc[nt][0], sacc[nt][1]));
            mx1 = fmaxf(mx1, fmaxf(sacc[nt][2], sacc[nt][3]));
        }
        // row (quad) max
        mx0 = fmaxf(mx0, __shfl_xor_sync(0xffffffffu, mx0, 1));
        mx0 = fmaxf(mx0, __shfl_xor_sync(0xffffffffu, mx0, 2));
        mx1 = fmaxf(mx1, __shfl_xor_sync(0xffffffffu, mx1, 1));
        mx1 = fmaxf(mx1, __shfl_xor_sync(0xffffffffu, mx1, 2));
        float mn0 = fmaxf(m0r, mx0), mn1 = fmaxf(m1r, mx1);
        float al0 = __expf(m0r - mn0), al1 = __expf(m1r - mn1);
        m0r = mn0; m1r = mn1;

        // p = exp(s - m), pack to half2 (A-fragment layout = C-fragment layout)
        uint32_t ph[16][2];
        float s0 = 0.f, s1 = 0.f;
        #pragma unroll
        for (int nt = 0; nt < 16; nt++) {
            float p0 = __expf(sacc[nt][0] - mn0);
            float p1 = __expf(sacc[nt][1] - mn0);
            float p2 = __expf(sacc[nt][2] - mn1);
            float p3 = __expf(sacc[nt][3] - mn1);
            s0 += p0 + p1; s1 += p2 + p3;
            __half2 h01 = __floats2half2_rn(p0, p1);
            __half2 h23 = __floats2half2_rn(p2, p3);
            ph[nt][0] = *reinterpret_cast<uint32_t*>(&h01);
            ph[nt][1] = *reinterpret_cast<uint32_t*>(&h23);
        }
        l0r = l0r * al0 + s0;
        l1r = l1r * al1 + s1;
        #pragma unroll
        for (int nt = 0; nt < 8; nt++) {
            oacc[nt][0] *= al0; oacc[nt][1] *= al0;
            oacc[nt][2] *= al1; oacc[nt][3] *= al1;
        }
        // O += P @ V  (fp16, K=128 in 8 chunks of 16)
        #pragma unroll
        for (int kc = 0; kc < 8; kc++) {
            uint32_t a0 = ph[2 * kc][0],     a1 = ph[2 * kc][1];
            uint32_t a2 = ph[2 * kc + 1][0], a3 = ph[2 * kc + 1][1];
            #pragma unroll
            for (int nt = 0; nt < 8; nt++) {
                uint32_t b0 = *reinterpret_cast<const uint32_t*>(&Vh[(kc * 8 + t) * 72 + nt * 8 + g]);
                uint32_t b1 = *reinterpret_cast<const uint32_t*>(&Vh[(kc * 8 + t + 4) * 72 + nt * 8 + g]);
                mma_f16(oacc[nt], a0, a1, a2, a3, b0, b1);
            }
        }
    }

    // finalize: l across quad, normalize, write ctx
    l0r += __shfl_xor_sync(0xffffffffu, l0r, 1);
    l0r += __shfl_xor_sync(0xffffffffu, l0r, 2);
    l1r += __shfl_xor_sync(0xffffffffu, l1r, 1);
    l1r += __shfl_xor_sync(0xffffffffu, l1r, 2);
    float inv0 = 1.f / l0r, inv1 = 1.f / l1r;
    float* C0 = ctx + ((size_t)b * SS + ig0) * DD + h * DHH + 2 * t;
    float* C1 = ctx + ((size_t)b * SS + ig1) * DD + h * DHH + 2 * t;
    #pragma unroll
    for (int nt = 0; nt < 8; nt++) {
        *reinterpret_cast<float2*>(C0 + nt * 8) = make_float2(oacc[nt][0] * inv0, oacc[nt][1] * inv0);
        *reinterpret_cast<float2*>(C1 + nt * 8) = make_float2(oacc[nt][2] * inv1, oacc[nt][3] * inv1);
    }
}

// ---------------------------------------------------------------------------
// Block reductions (256 threads)
// ---------------------------------------------------------------------------
__device__ __forceinline__ float bsum256(float v) {
    __shared__ float sm[8];
    #pragma unroll
    for (int o = 16; o; o >>= 1) v += __shfl_xor_sync(0xffffffffu, v, o);
    if ((threadIdx.x & 31) == 0) sm[threadIdx.x >> 5] = v;
    __syncthreads();
    float r = 0.f;
    #pragma unroll
    for (int i = 0; i < 8; i++) r += sm[i];
    __syncthreads();
    return r;
}

// ---------------------------------------------------------------------------
// Embedding
// ---------------------------------------------------------------------------
__global__ void embed_kernel(const int* __restrict__ token_ids,
                             const int* __restrict__ segment_ids,
                             const int* __restrict__ position_ids,
                             const int* __restrict__ question_mask,
                             const float* __restrict__ tok_emb,
                             const float* __restrict__ seg_emb,
                             float* __restrict__ x)
{
    int row = blockIdx.x;
    int tok = token_ids[row];
    int seg = segment_ids[row];
    int qmi = question_mask[row];
    float qm = (float)qmi;
    int pos = position_ids[row] * qmi;
    float fpos = (float)pos;

    const float* te = tok_emb + (size_t)tok * DD;
    const float* se = seg_emb + (size_t)seg * DD;
    float* xr = x + (size_t)row * DD;

    for (int i = threadIdx.x; i < DD; i += 256) {
        float ex  = (float)(2 * (i >> 1)) * (1.0f / (float)DD);
        float inv = __powf(10000.0f, -ex);
        float ang = fpos * inv;
        float pe  = (i & 1) ? cosf(ang) : sinf(ang);
        xr[i] = te[i] + se[i] + pe * qm;
    }
}

// ---------------------------------------------------------------------------
// LayerNorm
// ---------------------------------------------------------------------------
__global__ void ln_kernel(const float* __restrict__ x,
                          const float* __restrict__ gamma,
                          const float* __restrict__ beta,
                          float* __restrict__ out)
{
    int row = blockIdx.x;
    const float* xr = x + (size_t)row * DD;
    int t = threadIdx.x;
    float v0 = xr[t], v1 = xr[t + 256], v2 = xr[t + 512];

    float s = bsum256(v0 + v1 + v2);
    float mu = s * (1.0f / (float)DD);
    float d0 = v0 - mu, d1 = v1 - mu, d2 = v2 - mu;
    float s2 = bsum256(d0*d0 + d1*d1 + d2*d2);
    float var = s2 * (1.0f / (float)DD);
    float rstd = rsqrtf(var + 1e-12f);

    float* orow = out + (size_t)row * DD;
    orow[t]       = d0 * rstd * gamma[t]       + beta[t];
    orow[t + 256] = d1 * rstd * gamma[t + 256] + beta[t + 256];
    orow[t + 512] = d2 * rstd * gamma[t + 512] + beta[t + 512];
}

// ---------------------------------------------------------------------------
// Relative bias: rel[bh,i,r] = sum_d q[b,i,h,d] * rel_emb[r,h,d]
// ---------------------------------------------------------------------------
__global__ void rel_kernel(const float* __restrict__ q,
                           const float* __restrict__ relw,
                           float* __restrict__ rel)
{
    int bh = blockIdx.y;
    int b = bh / HH, h = bh % HH;
    int i0 = blockIdx.x * 8;

    __shared__ float Rs[RELV][65];
    __shared__ float Qs[8][DHH];

    int tid = threadIdx.x;
    #pragma unroll
    for (int e = 0; e < 8; e++) {
        int idx = tid + e * 256;
        int r = idx >> 6, d = idx & 63;
        Rs[r][d] = relw[((size_t)r * HH + h) * DHH + d];
    }
    #pragma unroll
    for (int e = 0; e < 2; e++) {
        int idx = tid + e * 256;
        int ii = idx >> 6, d = idx & 63;
        Qs[ii][d] = q[(size_t)b * SS * DD + (size_t)(i0 + ii) * DD + h * DHH + d];
    }
    __syncthreads();

    int r = tid & 31, iy = tid >> 5;
    float s = 0.f;
    #pragma unroll
    for (int d = 0; d < 64; d++) s += Qs[iy][d] * Rs[r][d];
    rel[((size_t)bh * SS + i0 + iy) * RELV + r] = s;
}

// ---------------------------------------------------------------------------
// Launch
// ---------------------------------------------------------------------------
extern "C" void kernel_launch(void* const* d_in, const int* in_sizes, int n_in,
                              void* d_out, int out_size)
{
    const int* token_ids     = (const int*)d_in[0];
    const int* segment_ids   = (const int*)d_in[1];
    const int* position_ids  = (const int*)d_in[2];
    const int* question_mask = (const int*)d_in[3];
    const int* attention_mask= (const int*)d_in[4];
    const int* rel_ids       = (const int*)d_in[5];
    const float* tok_emb = (const float*)d_in[6];
    const float* seg_emb = (const float*)d_in[7];
    const float* ln1_g = (const float*)d_in[8];
    const float* ln1_b = (const float*)d_in[9];
    const float* ln2_g = (const float*)d_in[10];
    const float* ln2_b = (const float*)d_in[11];
    const float* wq = (const float*)d_in[12];
    const float* bq = (const float*)d_in[13];
    const float* wk = (const float*)d_in[14];
    const float* bk = (const float*)d_in[15];
    const float* wv = (const float*)d_in[16];
    const float* bv = (const float*)d_in[17];
    const float* wo = (const float*)d_in[18];
    const float* bo = (const float*)d_in[19];
    const float* rel_emb = (const float*)d_in[20];
    const float* w1 = (const float*)d_in[21];
    const float* b1 = (const float*)d_in[22];
    const float* w2 = (const float*)d_in[23];
    const float* b2 = (const float*)d_in[24];

    float *x, *h, *q, *k, *v, *ctx, *rl, *ff;
    cudaGetSymbolAddress((void**)&x,   g_x);
    cudaGetSymbolAddress((void**)&h,   g_h);
    cudaGetSymbolAddress((void**)&q,   g_q);
    cudaGetSymbolAddress((void**)&k,   g_k);
    cudaGetSymbolAddress((void**)&v,   g_v);
    cudaGetSymbolAddress((void**)&ctx, g_ctx);
    cudaGetSymbolAddress((void**)&rl,  g_rel);
    cudaGetSymbolAddress((void**)&ff,  g_ffn);

    const int FLASH_SMEM = 80128;
    cudaFuncSetAttribute(flash_kernel,
                         cudaFuncAttributeMaxDynamicSharedMemorySize, FLASH_SMEM);

    embed_kernel<<<NROW, 256>>>(token_ids, segment_ids, position_ids,
                                question_mask, tok_emb, seg_emb, x);

    for (int l = 0; l < LL; l++) {
        const float* wq_l = wq + (size_t)l * DD * DD;
        const float* wk_l = wk + (size_t)l * DD * DD;
        const float* wv_l = wv + (size_t)l * DD * DD;
        const float* wo_l = wo + (size_t)l * DD * DD;
        const float* w1_l = w1 + (size_t)l * DD * FF;
        const float* w2_l = w2 + (size_t)l * FF * DD;

        // --- attention block ---
        ln_kernel<<<NROW, 256>>>(x, ln1_g + l * DD, ln1_b + l * DD, h);

        qkv_kernel<<<dim3(DD / 128, NROW / 128, 3), 256>>>(
            h, wq_l, wk_l, wv_l, bq + l * DD, bk + l * DD, bv + l * DD, q, k, v);

        rel_kernel<<<dim3(SS / 8, BB * HH), 256>>>(
            q, rel_emb + (size_t)l * RELV * HH * DHH, rl);

        flash_kernel<<<dim3(SS / 64, BB * HH), 128, FLASH_SMEM>>>(
            q, k, v, rl, rel_ids, attention_mask, ctx);

        mm_kernel<2><<<dim3(DD / 128, NROW / 128), 256>>>(
            ctx, DD, wo_l, DD, bo + l * DD, x, DD, x, DD, DD);

        // --- FFN block ---
        ln_kernel<<<NROW, 256>>>(x, ln2_g + l * DD, ln2_b + l * DD, h);
        mm_kernel<1><<<dim3(FF / 128, NROW / 128), 256>>>(
            h, DD, w1_l, FF, b1 + l * FF, nullptr, 0, ff, FF, DD);

        float* outp = (l == LL - 1) ? (float*)d_out : x;
        mm_kernel<2><<<dim3(DD / 128, NROW / 128), 256>>>(
            ff, FF, w2_l, DD, b2 + l * DD, x, DD, outp, DD, FF);
    }
}

// round 4
// speedup vs baseline: 2.8992x; 1.4212x over previous
#include <cuda_runtime.h>
#include <cuda_fp16.h>
#include <math.h>
#include <stdint.h>

// Problem constants
#define BB   2
#define SS   1024
#define DD   768
#define HH   12
#define DHH  64
#define LL   6
#define FF   3072
#define RELV 32
#define NROW (BB*SS)          // 2048 token rows

// ---------------------------------------------------------------------------
// Scratch (device globals; no dynamic allocation allowed)
// ---------------------------------------------------------------------------
__device__ float g_x  [NROW*DD];
__device__ float g_h  [NROW*DD];
__device__ float g_q  [NROW*DD];
__device__ float g_k  [NROW*DD];
__device__ float g_v  [NROW*DD];
__device__ float g_ctx[NROW*DD];
__device__ float g_rel[(size_t)BB*HH*SS*RELV];
__device__ float g_ffn[(size_t)NROW*FF];

// ---------------------------------------------------------------------------
// fp16 helpers
// ---------------------------------------------------------------------------
__device__ __forceinline__ void h_split(float v, __half& hi, __half& lo) {
    hi = __float2half_rn(v);
    lo = __float2half_rn(v - __half2float(hi));
}

__device__ __forceinline__ uint32_t ldh2(const __half* p) {
    return *reinterpret_cast<const uint32_t*>(p);
}

__device__ __forceinline__ void mma_f16(float c[4], uint32_t a0, uint32_t a1,
                                        uint32_t a2, uint32_t a3,
                                        uint32_t b0, uint32_t b1) {
    asm volatile(
        "mma.sync.aligned.m16n8k16.row.col.f32.f16.f16.f32 "
        "{%0,%1,%2,%3},{%4,%5,%6,%7},{%8,%9},{%0,%1,%2,%3};"
        : "+f"(c[0]), "+f"(c[1]), "+f"(c[2]), "+f"(c[3])
        : "r"(a0), "r"(a1), "r"(a2), "r"(a3), "r"(b0), "r"(b1));
}

__device__ __forceinline__ void mma_f16a(float c[4], const uint32_t a[4],
                                         uint32_t b0, uint32_t b1) {
    mma_f16(c, a[0], a[1], a[2], a[3], b0, b1);
}

__device__ __forceinline__ void ldsm4t(uint32_t& r0, uint32_t& r1,
                                       uint32_t& r2, uint32_t& r3, uint32_t a) {
    asm volatile("ldmatrix.sync.aligned.m8n8.x4.trans.shared.b16 {%0,%1,%2,%3}, [%4];"
                 : "=r"(r0), "=r"(r1), "=r"(r2), "=r"(r3) : "r"(a));
}

__device__ __forceinline__ float gelu_tanh(float v) {
    float u = 0.7978845608028654f * (v + 0.044715f * v * v * v);
    return 0.5f * v * (1.0f + tanhf(u));
}

// ---------------------------------------------------------------------------
// Tensor-core GEMM core: fp16x3 split (C += Ah.Bh + Al.Bh + Ah.Bl) => ~fp32
// C[M,N] = A[M,K] @ B[K,N] + epilogue. Block 256 thr = 8 warps. BK=16.
// A in smem as [m][k] half (direct half2 fragment loads, conflict-free);
// B in smem as [k][n] half, fragments via ldmatrix.x4.trans.
// EPI: 0=+bias, 1=+bias+gelu, 2=+bias+residual
// ---------------------------------------------------------------------------
template<int BM, int BN, int WM, int WN, int EPI>
__device__ __forceinline__ void gemm_core(
    const float* __restrict__ A, int lda,
    const float* __restrict__ B, int ldb,
    const float* __restrict__ bias,
    const float* __restrict__ R, int ldr,
    float* __restrict__ C, int ldc,
    int K, int m0, int n0)
{
    constexpr int NWN = BN / WN;
    constexpr int NMT = WM / 16;
    constexpr int NNT = WN / 8;
    constexpr int NA4 = (BM * 16) / 1024;
    constexpr int NB4 = (BN * 16) / 1024;
    constexpr int AKP = 24;              // halfs per A row (16 + 8 pad)
    constexpr int BNP = BN + 8;          // halfs per B row
    constexpr int ASZ = BM * AKP;        // halfs per (hi|lo) A buffer
    constexpr int BSZ = 16 * BNP;        // halfs per (hi|lo) B buffer

    __shared__ __align__(16) __half sh[2 * ASZ + 2 * BSZ];
    __half* Ah = sh;
    __half* Al = sh + ASZ;
    __half* Bh = sh + 2 * ASZ;
    __half* Bl = sh + 2 * ASZ + BSZ;

    const int tid  = threadIdx.x;
    const int lane = tid & 31;
    const int wid  = tid >> 5;
    const int g    = lane >> 2;
    const int t    = lane & 3;
    const int wm   = (wid / NWN) * WM;
    const int wn   = (wid % NWN) * WN;

    // ldmatrix lane mapping: k row + n column-half selector
    const int lk    = ((lane >> 3) & 1) * 8 + (lane & 7);
    const int lncol = ((lane >> 4) & 1) * 8;
    const uint32_t bhb = (uint32_t)__cvta_generic_to_shared(Bh);
    const uint32_t blb = (uint32_t)__cvta_generic_to_shared(Bl);

    const float* Ap = A + (size_t)m0 * lda;
    const float* Bp = B + n0;

    float acc[NMT][NNT][4];
    #pragma unroll
    for (int i = 0; i < NMT; i++)
        #pragma unroll
        for (int j = 0; j < NNT; j++)
            #pragma unroll
            for (int e = 0; e < 4; e++) acc[i][j][e] = 0.f;

    float4 rA[NA4], rB[NB4];

    auto gload = [&](int k0) {
        #pragma unroll
        for (int e = 0; e < NA4; e++) {
            int f = tid + e * 256;
            rA[e] = *reinterpret_cast<const float4*>(
                Ap + (size_t)(f >> 2) * lda + k0 + (f & 3) * 4);
        }
        #pragma unroll
        for (int e = 0; e < NB4; e++) {
            int f = tid + e * 256;
            rB[e] = *reinterpret_cast<const float4*>(
                Bp + (size_t)(k0 + f / (BN / 4)) * ldb + (f % (BN / 4)) * 4);
        }
    };

    auto sstore = [&]() {
        #pragma unroll
        for (int e = 0; e < NA4; e++) {
            int f = tid + e * 256; int m = f >> 2; int kq = (f & 3) * 4;
            float vv[4] = {rA[e].x, rA[e].y, rA[e].z, rA[e].w};
            __half hh[4], ll[4];
            #pragma unroll
            for (int i = 0; i < 4; i++) h_split(vv[i], hh[i], ll[i]);
            __half* pa = Ah + m * AKP + kq;
            __half* pl = Al + m * AKP + kq;
            *reinterpret_cast<__half2*>(pa)     = __halves2half2(hh[0], hh[1]);
            *reinterpret_cast<__half2*>(pa + 2) = __halves2half2(hh[2], hh[3]);
            *reinterpret_cast<__half2*>(pl)     = __halves2half2(ll[0], ll[1]);
            *reinterpret_cast<__half2*>(pl + 2) = __halves2half2(ll[2], ll[3]);
        }
        #pragma unroll
        for (int e = 0; e < NB4; e++) {
            int f = tid + e * 256; int kk = f / (BN / 4); int nq = (f % (BN / 4)) * 4;
            float vv[4] = {rB[e].x, rB[e].y, rB[e].z, rB[e].w};
            __half hh[4], ll[4];
            #pragma unroll
            for (int i = 0; i < 4; i++) h_split(vv[i], hh[i], ll[i]);
            __half* pb = Bh + kk * BNP + nq;
            __half* pl = Bl + kk * BNP + nq;
            *reinterpret_cast<__half2*>(pb)     = __halves2half2(hh[0], hh[1]);
            *reinterpret_cast<__half2*>(pb + 2) = __halves2half2(hh[2], hh[3]);
            *reinterpret_cast<__half2*>(pl)     = __halves2half2(ll[0], ll[1]);
            *reinterpret_cast<__half2*>(pl + 2) = __halves2half2(ll[2], ll[3]);
        }
    };

    gload(0);
    sstore();
    __syncthreads();

    const int ntiles = K >> 4;
    for (int kt = 0; kt < ntiles; kt++) {
        const bool more = (kt + 1 < ntiles);
        if (more) gload((kt + 1) << 4);

        // A fragments (hi/lo), one k16 per stage
        uint32_t ah[NMT][4], al[NMT][4];
        #pragma unroll
        for (int mt = 0; mt < NMT; mt++) {
            int r = wm + mt * 16 + g;
            const __half* Ar  = Ah + r * AKP;
            const __half* Ar8 = Ah + (r + 8) * AKP;
            ah[mt][0] = ldh2(Ar  + 2 * t);
            ah[mt][1] = ldh2(Ar8 + 2 * t);
            ah[mt][2] = ldh2(Ar  + 2 * t + 8);
            ah[mt][3] = ldh2(Ar8 + 2 * t + 8);
            const __half* Lr  = Al + r * AKP;
            const __half* Lr8 = Al + (r + 8) * AKP;
            al[mt][0] = ldh2(Lr  + 2 * t);
            al[mt][1] = ldh2(Lr8 + 2 * t);
            al[mt][2] = ldh2(Lr  + 2 * t + 8);
            al[mt][3] = ldh2(Lr8 + 2 * t + 8);
        }

        #pragma unroll
        for (int np = 0; np < NNT / 2; np++) {
            uint32_t off = (uint32_t)(lk * BNP + wn + np * 16 + lncol) * 2;
            uint32_t b0, b1, b2, b3, c0, c1, c2, c3;
            ldsm4t(b0, b1, b2, b3, bhb + off);
            ldsm4t(c0, c1, c2, c3, blb + off);
            #pragma unroll
            for (int mt = 0; mt < NMT; mt++) {
                mma_f16a(acc[mt][2 * np],     ah[mt], b0, b1);
                mma_f16a(acc[mt][2 * np],     al[mt], b0, b1);
                mma_f16a(acc[mt][2 * np],     ah[mt], c0, c1);
                mma_f16a(acc[mt][2 * np + 1], ah[mt], b2, b3);
                mma_f16a(acc[mt][2 * np + 1], al[mt], b2, b3);
                mma_f16a(acc[mt][2 * np + 1], ah[mt], c2, c3);
            }
        }
        __syncthreads();
        if (more) { sstore(); __syncthreads(); }
    }

    // Epilogue
    #pragma unroll
    for (int mt = 0; mt < NMT; mt++) {
        int r0 = m0 + wm + mt * 16 + g;
        #pragma unroll
        for (int nt = 0; nt < NNT; nt++) {
            int cc = n0 + wn + nt * 8 + t * 2;
            float2 p0 = make_float2(acc[mt][nt][0], acc[mt][nt][1]);
            float2 p1 = make_float2(acc[mt][nt][2], acc[mt][nt][3]);
            float b0 = bias[cc], b1 = bias[cc + 1];
            p0.x += b0; p0.y += b1; p1.x += b0; p1.y += b1;
            if (EPI == 1) {
                p0.x = gelu_tanh(p0.x); p0.y = gelu_tanh(p0.y);
                p1.x = gelu_tanh(p1.x); p1.y = gelu_tanh(p1.y);
            }
            if (EPI == 2) {
                p0.x += R[(size_t)r0 * ldr + cc];
                p0.y += R[(size_t)r0 * ldr + cc + 1];
                p1.x += R[(size_t)(r0 + 8) * ldr + cc];
                p1.y += R[(size_t)(r0 + 8) * ldr + cc + 1];
            }
            *reinterpret_cast<float2*>(&C[(size_t)r0 * ldc + cc]) = p0;
            *reinterpret_cast<float2*>(&C[(size_t)(r0 + 8) * ldc + cc]) = p1;
        }
    }
}

// QKV fused via blockIdx.z
__global__ __launch_bounds__(256, 1)
void qkv_kernel(const float* __restrict__ h,
                const float* __restrict__ wq, const float* __restrict__ wk,
                const float* __restrict__ wv,
                const float* __restrict__ bq, const float* __restrict__ bk,
                const float* __restrict__ bv,
                float* __restrict__ q, float* __restrict__ k, float* __restrict__ v)
{
    int z = blockIdx.z;
    const float* W  = (z == 0) ? wq : (z == 1) ? wk : wv;
    const float* bi = (z == 0) ? bq : (z == 1) ? bk : bv;
    float* C        = (z == 0) ? q  : (z == 1) ? k  : v;
    gemm_core<128,128,64,32,0>(h, DD, W, DD, bi, nullptr, 0, C, DD,
                               DD, blockIdx.y * 128, blockIdx.x * 128);
}

template<int EPI>
__global__ __launch_bounds__(256, 1)
void mm_kernel(const float* __restrict__ A, int lda,
               const float* __restrict__ B, int ldb,
               const float* __restrict__ bias,
               const float* __restrict__ R, int ldr,
               float* __restrict__ C, int ldc, int K)
{
    gemm_core<128,128,64,32,EPI>(A, lda, B, ldb, bias, R, ldr, C, ldc,
                                 K, blockIdx.y * 128, blockIdx.x * 128);
}

// ---------------------------------------------------------------------------
// Fused flash attention: per CTA = 64 query rows of one (b,h).
// 128 threads = 4 warps, warp tile 16(i) x 128(j). Online softmax.
// S = QK^T via fp16x3 split; P.V via fp16 with register-resident P.
// ---------------------------------------------------------------------------
__global__ __launch_bounds__(128, 2)
void flash_kernel(const float* __restrict__ q, const float* __restrict__ k,
                  const float* __restrict__ v, const float* __restrict__ rel,
                  const int* __restrict__ rel_ids, const int* __restrict__ mask,
                  float* __restrict__ ctx)
{
    extern __shared__ float smf[];
    __half*  Qh = reinterpret_cast<__half*>(smf);            // [64][72] halfs
    __half*  Ql = Qh + 4608;
    __half*  Kh = Ql + 4608;                                 // [128][72] halfs
    __half*  Kl = Kh + 9216;
    __half2* Vh = reinterpret_cast<__half2*>(Kl + 9216);     // [64 jp][72 d]
    float*   rels = reinterpret_cast<float*>(Vh + 4608);     // [64][33]

    const int tid  = threadIdx.x;
    const int lane = tid & 31;
    const int wid  = tid >> 5;
    const int g = lane >> 2, t = lane & 3;
    const int wm = wid << 4;

    const int i0 = blockIdx.x * 64;
    const int bh = blockIdx.y;
    const int b = bh / HH, h = bh - b * HH;

    const float* Qp = q + (size_t)b * SS * DD + h * DHH;
    const float* Kp = k + (size_t)b * SS * DD + h * DHH;
    const float* Vp = v + (size_t)b * SS * DD + h * DHH;

    // Q tile -> Qh/Ql [row][d]
    {
        int row = tid & 63;
        int base = (tid >> 6) * 8;
        #pragma unroll
        for (int e = 0; e < 8; e++) {
            int dq = (base + e) * 4;
            float4 val = *reinterpret_cast<const float4*>(Qp + (size_t)(i0 + row) * DD + dq);
            float vv[4] = {val.x, val.y, val.z, val.w};
            __half hh[4], ll[4];
            #pragma unroll
            for (int i = 0; i < 4; i++) h_split(vv[i], hh[i], ll[i]);
            __half* ph = Qh + row * 72 + dq;
            __half* pl = Ql + row * 72 + dq;
            *reinterpret_cast<__half2*>(ph)     = __halves2half2(hh[0], hh[1]);
            *reinterpret_cast<__half2*>(ph + 2) = __halves2half2(hh[2], hh[3]);
            *reinterpret_cast<__half2*>(pl)     = __halves2half2(ll[0], ll[1]);
            *reinterpret_cast<__half2*>(pl + 2) = __halves2half2(ll[2], ll[3]);
        }
    }
    // rel rows (precomputed) -> rels[row][r]
    {
        const float* rp = rel + ((size_t)bh * SS + i0) * RELV;
        #pragma unroll
        for (int e = 0; e < 4; e++) {
            int f = tid + e * 128;
            float4 val = *reinterpret_cast<const float4*>(rp + f * 4);
            int row = f >> 3, r = (f & 7) * 4;
            rels[row * 33 + r + 0] = val.x;
            rels[row * 33 + r + 1] = val.y;
            rels[row * 33 + r + 2] = val.z;
            rels[row * 33 + r + 3] = val.w;
        }
    }
    __syncthreads();

    // Hoisted Q fragments (4 k16 chunks)
    uint32_t qfh[4][4], qfl[4][4];
    #pragma unroll
    for (int kc = 0; kc < 4; kc++) {
        int kb = kc * 16;
        const __half* r0h = Qh + (wm + g) * 72 + kb;
        const __half* r8h = r0h + 8 * 72;
        qfh[kc][0] = ldh2(r0h + 2 * t);
        qfh[kc][1] = ldh2(r8h + 2 * t);
        qfh[kc][2] = ldh2(r0h + 2 * t + 8);
        qfh[kc][3] = ldh2(r8h + 2 * t + 8);
        const __half* r0l = Ql + (wm + g) * 72 + kb;
        const __half* r8l = r0l + 8 * 72;
        qfl[kc][0] = ldh2(r0l + 2 * t);
        qfl[kc][1] = ldh2(r8l + 2 * t);
        qfl[kc][2] = ldh2(r0l + 2 * t + 8);
        qfl[kc][3] = ldh2(r8l + 2 * t + 8);
    }

    float m0r = -1e30f, m1r = -1e30f;
    float l0r = 0.f, l1r = 0.f;
    float oacc[8][4];
    #pragma unroll
    for (int nt = 0; nt < 8; nt++) {
        oacc[nt][0] = 0.f; oacc[nt][1] = 0.f; oacc[nt][2] = 0.f; oacc[nt][3] = 0.f;
    }

    const int ig0 = i0 + wm + g;
    const int ig1 = ig0 + 8;
    const int* rid0 = rel_ids + ((size_t)b * SS + ig0) * SS + 2 * t;
    const int* rid1 = rel_ids + ((size_t)b * SS + ig1) * SS + 2 * t;
    const int* mk0  = mask    + ((size_t)b * SS + ig0) * SS + 2 * t;
    const int* mk1  = mask    + ((size_t)b * SS + ig1) * SS + 2 * t;
    const float* rl0 = rels + (wm + g) * 33;
    const float* rl1 = rl0 + 8 * 33;

    for (int jt = 0; jt < 8; jt++) {
        const int j0 = jt * 128;
        __syncthreads();
        // K tile -> Kh/Kl [j][d]
        #pragma unroll
        for (int e = 0; e < 16; e++) {
            int dq = e * 4;
            float4 val = *reinterpret_cast<const float4*>(Kp + (size_t)(j0 + tid) * DD + dq);
            float vv[4] = {val.x, val.y, val.z, val.w};
            __half hh[4], ll[4];
            #pragma unroll
            for (int i = 0; i < 4; i++) h_split(vv[i], hh[i], ll[i]);
            __half* ph = Kh + tid * 72 + dq;
            __half* pl = Kl + tid * 72 + dq;
            *reinterpret_cast<__half2*>(ph)     = __halves2half2(hh[0], hh[1]);
            *reinterpret_cast<__half2*>(ph + 2) = __halves2half2(hh[2], hh[3]);
            *reinterpret_cast<__half2*>(pl)     = __halves2half2(ll[0], ll[1]);
            *reinterpret_cast<__half2*>(pl + 2) = __halves2half2(ll[2], ll[3]);
        }
        // V tile -> Vh[jpair][d] as half2(v_j, v_{j+1})
        #pragma unroll
        for (int e = 0; e < 8; e++) {
            int f = tid + e * 128;
            int jp = f >> 4, dq = (f & 15) * 4;
            float4 v0 = *reinterpret_cast<const float4*>(Vp + (size_t)(j0 + 2 * jp) * DD + dq);
            float4 v1 = *reinterpret_cast<const float4*>(Vp + (size_t)(j0 + 2 * jp + 1) * DD + dq);
            __half2* dst = Vh + jp * 72 + dq;
            dst[0] = __floats2half2_rn(v0.x, v1.x);
            dst[1] = __floats2half2_rn(v0.y, v1.y);
            dst[2] = __floats2half2_rn(v0.z, v1.z);
            dst[3] = __floats2half2_rn(v0.w, v1.w);
        }
        __syncthreads();

        // S = Q K^T, 16 n8-tiles per warp, fp16x3
        float sacc[16][4];
        #pragma unroll
        for (int nt = 0; nt < 16; nt++) {
            sacc[nt][0] = 0.f; sacc[nt][1] = 0.f; sacc[nt][2] = 0.f; sacc[nt][3] = 0.f;
        }
        #pragma unroll
        for (int kc = 0; kc < 4; kc++) {
            int kb = kc * 16;
            #pragma unroll
            for (int nt = 0; nt < 16; nt++) {
                const __half* nbh = Kh + (nt * 8 + g) * 72 + kb;
                const __half* nbl = Kl + (nt * 8 + g) * 72 + kb;
                uint32_t b0 = ldh2(nbh + 2 * t);
                uint32_t b1 = ldh2(nbh + 2 * t + 8);
                uint32_t c0 = ldh2(nbl + 2 * t);
                uint32_t c1 = ldh2(nbl + 2 * t + 8);
                mma_f16a(sacc[nt], qfh[kc], b0, b1);
                mma_f16a(sacc[nt], qfl[kc], b0, b1);
                mma_f16a(sacc[nt], qfh[kc], c0, c1);
            }
        }

        // rel-bias gather + mask + scale
        float mx0 = -1e30f, mx1 = -1e30f;
        #pragma unroll
        for (int nt = 0; nt < 16; nt++) {
            int jo = j0 + nt * 8;
            int2 i0v = *reinterpret_cast<const int2*>(rid0 + jo);
            int2 i1v = *reinterpret_cast<const int2*>(rid1 + jo);
            int2 m0v = *reinterpret_cast<const int2*>(mk0 + jo);
            int2 m1v = *reinterpret_cast<const int2*>(mk1 + jo);
            sacc[nt][0] = (sacc[nt][0] + rl0[i0v.x]) * 0.125f + (1.f - (float)m0v.x) * -10000.f;
            sacc[nt][1] = (sacc[nt][1] + rl0[i0v.y]) * 0.125f + (1.f - (float)m0v.y) * -10000.f;
            sacc[nt][2] = (sacc[nt][2] + rl1[i1v.x]) * 0.125f + (1.f - (float)m1v.x) * -10000.f;
            sacc[nt][3] = (sacc[nt][3] + rl1[i1v.y]) * 0.125f + (1.f - (float)m1v.y) * -10000.f;
            mx0 = fmaxf(mx0, fmaxf(sacc[nt][0], sacc[nt][1]));
            mx1 = fmaxf(mx1, fmaxf(sacc[nt][2], sacc[nt][3]));
        }
        mx0 = fmaxf(mx0, __shfl_xor_sync(0xffffffffu, mx0, 1));
        mx0 = fmaxf(mx0, __shfl_xor_sync(0xffffffffu, mx0, 2));
        mx1 = fmaxf(mx1, __shfl_xor_sync(0xffffffffu, mx1, 1));
        mx1 = fmaxf(mx1, __shfl_xor_sync(0xffffffffu, mx1, 2));
        float mn0 = fmaxf(m0r, mx0), mn1 = fmaxf(m1r, mx1);
        float al0 = __expf(m0r - mn0), al1 = __expf(m1r - mn1);
        m0r = mn0; m1r = mn1;

        // p = exp(s - m), pack to half2 (A-fragment layout = C-fragment layout)
        uint32_t ph[16][2];
        float s0 = 0.f, s1 = 0.f;
        #pragma unroll
        for (int nt = 0; nt < 16; nt++) {
            float p0 = __expf(sacc[nt][0] - mn0);
            float p1 = __expf(sacc[nt][1] - mn0);
            float p2 = __expf(sacc[nt][2] - mn1);
            float p3 = __expf(sacc[nt][3] - mn1);
            s0 += p0 + p1; s1 += p2 + p3;
            __half2 h01 = __floats2half2_rn(p0, p1);
            __half2 h23 = __floats2half2_rn(p2, p3);
            ph[nt][0] = *reinterpret_cast<uint32_t*>(&h01);
            ph[nt][1] = *reinterpret_cast<uint32_t*>(&h23);
        }
        l0r = l0r * al0 + s0;
        l1r = l1r * al1 + s1;
        #pragma unroll
        for (int nt = 0; nt < 8; nt++) {
            oacc[nt][0] *= al0; oacc[nt][1] *= al0;
            oacc[nt][2] *= al1; oacc[nt][3] *= al1;
        }
        // O += P @ V  (fp16, K=128 in 8 chunks of 16)
        #pragma unroll
        for (int kc = 0; kc < 8; kc++) {
            uint32_t a0 = ph[2 * kc][0],     a1 = ph[2 * kc][1];
            uint32_t a2 = ph[2 * kc + 1][0], a3 = ph[2 * kc + 1][1];
            #pragma unroll
            for (int nt = 0; nt < 8; nt++) {
                uint32_t b0 = *reinterpret_cast<const uint32_t*>(&Vh[(kc * 8 + t) * 72 + nt * 8 + g]);
                uint32_t b1 = *reinterpret_cast<const uint32_t*>(&Vh[(kc * 8 + t + 4) * 72 + nt * 8 + g]);
                mma_f16(oacc[nt], a0, a1, a2, a3, b0, b1);
            }
        }
    }

    // finalize: l across quad, normalize, write ctx
    l0r += __shfl_xor_sync(0xffffffffu, l0r, 1);
    l0r += __shfl_xor_sync(0xffffffffu, l0r, 2);
    l1r += __shfl_xor_sync(0xffffffffu, l1r, 1);
    l1r += __shfl_xor_sync(0xffffffffu, l1r, 2);
    float inv0 = 1.f / l0r, inv1 = 1.f / l1r;
    float* C0 = ctx + ((size_t)b * SS + ig0) * DD + h * DHH + 2 * t;
    float* C1 = ctx + ((size_t)b * SS + ig1) * DD + h * DHH + 2 * t;
    #pragma unroll
    for (int nt = 0; nt < 8; nt++) {
        *reinterpret_cast<float2*>(C0 + nt * 8) = make_float2(oacc[nt][0] * inv0, oacc[nt][1] * inv0);
        *reinterpret_cast<float2*>(C1 + nt * 8) = make_float2(oacc[nt][2] * inv1, oacc[nt][3] * inv1);
    }
}

// ---------------------------------------------------------------------------
// Block reductions (256 threads)
// ---------------------------------------------------------------------------
__device__ __forceinline__ float bsum256(float v) {
    __shared__ float sm[8];
    #pragma unroll
    for (int o = 16; o; o >>= 1) v += __shfl_xor_sync(0xffffffffu, v, o);
    if ((threadIdx.x & 31) == 0) sm[threadIdx.x >> 5] = v;
    __syncthreads();
    float r = 0.f;
    #pragma unroll
    for (int i = 0; i < 8; i++) r += sm[i];
    __syncthreads();
    return r;
}

// ---------------------------------------------------------------------------
// Embedding
// ---------------------------------------------------------------------------
__global__ void embed_kernel(const int* __restrict__ token_ids,
                             const int* __restrict__ segment_ids,
                             const int* __restrict__ position_ids,
                             const int* __restrict__ question_mask,
                             const float* __restrict__ tok_emb,
                             const float* __restrict__ seg_emb,
                             float* __restrict__ x)
{
    int row = blockIdx.x;
    int tok = token_ids[row];
    int seg = segment_ids[row];
    int qmi = question_mask[row];
    float qm = (float)qmi;
    int pos = position_ids[row] * qmi;
    float fpos = (float)pos;

    const float* te = tok_emb + (size_t)tok * DD;
    const float* se = seg_emb + (size_t)seg * DD;
    float* xr = x + (size_t)row * DD;

    for (int i = threadIdx.x; i < DD; i += 256) {
        float ex  = (float)(2 * (i >> 1)) * (1.0f / (float)DD);
        float inv = __powf(10000.0f, -ex);
        float ang = fpos * inv;
        float pe  = (i & 1) ? cosf(ang) : sinf(ang);
        xr[i] = te[i] + se[i] + pe * qm;
    }
}

// ---------------------------------------------------------------------------
// LayerNorm
// ---------------------------------------------------------------------------
__global__ void ln_kernel(const float* __restrict__ x,
                          const float* __restrict__ gamma,
                          const float* __restrict__ beta,
                          float* __restrict__ out)
{
    int row = blockIdx.x;
    const float* xr = x + (size_t)row * DD;
    int t = threadIdx.x;
    float v0 = xr[t], v1 = xr[t + 256], v2 = xr[t + 512];

    float s = bsum256(v0 + v1 + v2);
    float mu = s * (1.0f / (float)DD);
    float d0 = v0 - mu, d1 = v1 - mu, d2 = v2 - mu;
    float s2 = bsum256(d0*d0 + d1*d1 + d2*d2);
    float var = s2 * (1.0f / (float)DD);
    float rstd = rsqrtf(var + 1e-12f);

    float* orow = out + (size_t)row * DD;
    orow[t]       = d0 * rstd * gamma[t]       + beta[t];
    orow[t + 256] = d1 * rstd * gamma[t + 256] + beta[t + 256];
    orow[t + 512] = d2 * rstd * gamma[t + 512] + beta[t + 512];
}

// ---------------------------------------------------------------------------
// Relative bias: rel[bh,i,r] = sum_d q[b,i,h,d] * rel_emb[r,h,d]
// ---------------------------------------------------------------------------
__global__ void rel_kernel(const float* __restrict__ q,
                           const float* __restrict__ relw,
                           float* __restrict__ rel)
{
    int bh = blockIdx.y;
    int b = bh / HH, h = bh % HH;
    int i0 = blockIdx.x * 8;

    __shared__ float Rs[RELV][65];
    __shared__ float Qs[8][DHH];

    int tid = threadIdx.x;
    #pragma unroll
    for (int e = 0; e < 8; e++) {
        int idx = tid + e * 256;
        int r = idx >> 6, d = idx & 63;
        Rs[r][d] = relw[((size_t)r * HH + h) * DHH + d];
    }
    #pragma unroll
    for (int e = 0; e < 2; e++) {
        int idx = tid + e * 256;
        int ii = idx >> 6, d = idx & 63;
        Qs[ii][d] = q[(size_t)b * SS * DD + (size_t)(i0 + ii) * DD + h * DHH + d];
    }
    __syncthreads();

    int r = tid & 31, iy = tid >> 5;
    float s = 0.f;
    #pragma unroll
    for (int d = 0; d < 64; d++) s += Qs[iy][d] * Rs[r][d];
    rel[((size_t)bh * SS + i0 + iy) * RELV + r] = s;
}

// ---------------------------------------------------------------------------
// Launch
// ---------------------------------------------------------------------------
extern "C" void kernel_launch(void* const* d_in, const int* in_sizes, int n_in,
                              void* d_out, int out_size)
{
    const int* token_ids     = (const int*)d_in[0];
    const int* segment_ids   = (const int*)d_in[1];
    const int* position_ids  = (const int*)d_in[2];
    const int* question_mask = (const int*)d_in[3];
    const int* attention_mask= (const int*)d_in[4];
    const int* rel_ids       = (const int*)d_in[5];
    const float* tok_emb = (const float*)d_in[6];
    const float* seg_emb = (const float*)d_in[7];
    const float* ln1_g = (const float*)d_in[8];
    const float* ln1_b = (const float*)d_in[9];
    const float* ln2_g = (const float*)d_in[10];
    const float* ln2_b = (const float*)d_in[11];
    const float* wq = (const float*)d_in[12];
    const float* bq = (const float*)d_in[13];
    const float* wk = (const float*)d_in[14];
    const float* bk = (const float*)d_in[15];
    const float* wv = (const float*)d_in[16];
    const float* bv = (const float*)d_in[17];
    const float* wo = (const float*)d_in[18];
    const float* bo = (const float*)d_in[19];
    const float* rel_emb = (const float*)d_in[20];
    const float* w1 = (const float*)d_in[21];
    const float* b1 = (const float*)d_in[22];
    const float* w2 = (const float*)d_in[23];
    const float* b2 = (const float*)d_in[24];

    float *x, *h, *q, *k, *v, *ctx, *rl, *ff;
    cudaGetSymbolAddress((void**)&x,   g_x);
    cudaGetSymbolAddress((void**)&h,   g_h);
    cudaGetSymbolAddress((void**)&q,   g_q);
    cudaGetSymbolAddress((void**)&k,   g_k);
    cudaGetSymbolAddress((void**)&v,   g_v);
    cudaGetSymbolAddress((void**)&ctx, g_ctx);
    cudaGetSymbolAddress((void**)&rl,  g_rel);
    cudaGetSymbolAddress((void**)&ff,  g_ffn);

    const int FLASH_SMEM = 82176;
    cudaFuncSetAttribute(flash_kernel,
                         cudaFuncAttributeMaxDynamicSharedMemorySize, FLASH_SMEM);

    embed_kernel<<<NROW, 256>>>(token_ids, segment_ids, position_ids,
                                question_mask, tok_emb, seg_emb, x);

    for (int l = 0; l < LL; l++) {
        const float* wq_l = wq + (size_t)l * DD * DD;
        const float* wk_l = wk + (size_t)l * DD * DD;
        const float* wv_l = wv + (size_t)l * DD * DD;
        const float* wo_l = wo + (size_t)l * DD * DD;
        const float* w1_l = w1 + (size_t)l * DD * FF;
        const float* w2_l = w2 + (size_t)l * FF * DD;

        // --- attention block ---
        ln_kernel<<<NROW, 256>>>(x, ln1_g + l * DD, ln1_b + l * DD, h);

        qkv_kernel<<<dim3(DD / 128, NROW / 128, 3), 256>>>(
            h, wq_l, wk_l, wv_l, bq + l * DD, bk + l * DD, bv + l * DD, q, k, v);

        rel_kernel<<<dim3(SS / 8, BB * HH), 256>>>(
            q, rel_emb + (size_t)l * RELV * HH * DHH, rl);

        flash_kernel<<<dim3(SS / 64, BB * HH), 128, FLASH_SMEM>>>(
            q, k, v, rl, rel_ids, attention_mask, ctx);

        mm_kernel<2><<<dim3(DD / 128, NROW / 128), 256>>>(
            ctx, DD, wo_l, DD, bo + l * DD, x, DD, x, DD, DD);

        // --- FFN block ---
        ln_kernel<<<NROW, 256>>>(x, ln2_g + l * DD, ln2_b + l * DD, h);
        mm_kernel<1><<<dim3(FF / 128, NROW / 128), 256>>>(
            h, DD, w1_l, FF, b1 + l * FF, nullptr, 0, ff, FF, DD);

        float* outp = (l == LL - 1) ? (float*)d_out : x;
        mm_kernel<2><<<dim3(DD / 128, NROW / 128), 256>>>(
            ff, FF, w2_l, DD, b2 + l * DD, x, DD, outp, DD, FF);
    }
}